// round 6
// baseline (speedup 1.0000x reference)
#include <cuda_runtime.h>
#include <cuda_bf16.h>
#include <math.h>
#include <cstdint>

#define Bb 8
#define Nn 4096
#define Dd 256
#define Ee 65536
#define NODES (Bb * Nn)        // 32768
#define EDGES (Bb * Ee)        // 524288
#define G3D   (3 * Dd)         // 768

// ---------------- scratch (static device globals; no allocation) -------------
__device__ float d_Wct[G3D * Dd];                  // (Wih @ W^T), permuted rows
__device__ __nv_bfloat16 d_xhi[NODES * Dd];
__device__ __nv_bfloat16 d_xlo[NODES * Dd];
__device__ __nv_bfloat16 d_agghi[NODES * Dd];
__device__ __nv_bfloat16 d_agglo[NODES * Dd];
__device__ __nv_bfloat16 d_Whi[Dd * Dd];           // W plain split
__device__ __nv_bfloat16 d_Wlo[Dd * Dd];
__device__ __nv_bfloat16 d_Wihphi[G3D * Dd];       // Wih, rows permuted
__device__ __nv_bfloat16 d_Wihplo[G3D * Dd];
__device__ __nv_bfloat16 d_Whhphi[G3D * Dd];       // Whh, rows permuted
__device__ __nv_bfloat16 d_Whhplo[G3D * Dd];
__device__ __nv_bfloat16 d_Wcthi[G3D * Dd];
__device__ __nv_bfloat16 d_Wctlo[G3D * Dd];
__device__ float d_bihp[G3D];
__device__ float d_bhhp[G3D];
__device__ int   d_counts[NODES];
__device__ int   d_cursor[NODES];
__device__ int   d_rowptr[NODES + 1];
__device__ int   d_esrc[EDGES];
__device__ float d_eww[EDGES];

// permutation: orig row o = g*256+d  ->  o' = (d>>5)*96 + g*32 + (d&31)

// ---------------- CSR construction -------------------------------------------
__global__ void k_zero() {
    int i = blockIdx.x * blockDim.x + threadIdx.x;
    if (i < NODES) { d_counts[i] = 0; d_cursor[i] = 0; }
}

__global__ void k_count(const int* __restrict__ ei, const int* __restrict__ mask) {
    int idx = blockIdx.x * blockDim.x + threadIdx.x;
    if (idx >= EDGES) return;
    int b = idx >> 16;
    int e = idx & (Ee - 1);
    int u = ei[((b << 1) + 0) * Ee + e];
    int v = ei[((b << 1) + 1) * Ee + e];
    if (mask[(b << 12) + u] > 0 && mask[(b << 12) + v] > 0)
        atomicAdd(&d_counts[(b << 12) + v], 1);
}

__global__ void k_scan() {
    __shared__ int sums[1024];
    int t = threadIdx.x;
    int base = t * 32;
    int s = 0;
    #pragma unroll
    for (int i = 0; i < 32; i++) s += d_counts[base + i];
    sums[t] = s;
    __syncthreads();
    for (int off = 1; off < 1024; off <<= 1) {
        int v = (t >= off) ? sums[t - off] : 0;
        __syncthreads();
        sums[t] += v;
        __syncthreads();
    }
    int run = (t == 0) ? 0 : sums[t - 1];
    #pragma unroll
    for (int i = 0; i < 32; i++) {
        d_rowptr[base + i] = run;
        run += d_counts[base + i];
    }
    if (t == 1023) d_rowptr[NODES] = sums[1023];
}

__global__ void k_fill(const int* __restrict__ ei, const int* __restrict__ mask,
                       const float* __restrict__ ew) {
    int idx = blockIdx.x * blockDim.x + threadIdx.x;
    if (idx >= EDGES) return;
    int b = idx >> 16;
    int e = idx & (Ee - 1);
    int u = ei[((b << 1) + 0) * Ee + e];
    int v = ei[((b << 1) + 1) * Ee + e];
    if (mask[(b << 12) + u] > 0 && mask[(b << 12) + v] > 0) {
        int node = (b << 12) + v;
        int pos = d_rowptr[node] + atomicAdd(&d_cursor[node], 1);
        d_esrc[pos] = u;
        d_eww[pos]  = ew[idx];
    }
}

// ---------------- split helpers -----------------------------------------------
__device__ __forceinline__ void split2(float a, float b, __nv_bfloat162& hi, __nv_bfloat162& lo) {
    hi = __floats2bfloat162_rn(a, b);
    lo = __floats2bfloat162_rn(a - __bfloat162float(__low2bfloat16(hi)),
                               b - __bfloat162float(__high2bfloat16(hi)));
}

__global__ void k_split_x(const float* __restrict__ x) {
    int idx = blockIdx.x * blockDim.x + threadIdx.x;
    if (idx >= NODES * Dd / 2) return;
    float2 v = ((const float2*)x)[idx];
    __nv_bfloat162 h, l;
    split2(v.x, v.y, h, l);
    ((__nv_bfloat162*)d_xhi)[idx] = h;
    ((__nv_bfloat162*)d_xlo)[idx] = l;
}

__global__ void k_split_W(const float* __restrict__ W) {
    int idx = blockIdx.x * blockDim.x + threadIdx.x;
    if (idx >= Dd * Dd / 2) return;
    float2 v = ((const float2*)W)[idx];
    __nv_bfloat162 h, l;
    split2(v.x, v.y, h, l);
    ((__nv_bfloat162*)d_Whi)[idx] = h;
    ((__nv_bfloat162*)d_Wlo)[idx] = l;
}

// permuted-row split of Wih/Whh + permuted biases
__global__ void k_permsplit(const float* __restrict__ wih, const float* __restrict__ whh,
                            const float* __restrict__ bih, const float* __restrict__ bhh) {
    int idx = blockIdx.x * blockDim.x + threadIdx.x;   // G3D * Dd/2
    if (idx >= G3D * Dd / 2) return;
    int o    = idx / (Dd / 2);
    int col2 = idx - o * (Dd / 2);
    int g = o >> 8, d = o & 255;
    int op = (d >> 5) * 96 + g * 32 + (d & 31);
    size_t dst = (size_t)op * (Dd / 2) + col2;
    float2 a = ((const float2*)wih)[idx];
    __nv_bfloat162 h, l;
    split2(a.x, a.y, h, l);
    ((__nv_bfloat162*)d_Wihphi)[dst] = h;
    ((__nv_bfloat162*)d_Wihplo)[dst] = l;
    float2 b = ((const float2*)whh)[idx];
    split2(b.x, b.y, h, l);
    ((__nv_bfloat162*)d_Whhphi)[dst] = h;
    ((__nv_bfloat162*)d_Whhplo)[dst] = l;
    if (col2 == 0) {
        d_bihp[op] = bih[o];
        d_bhhp[op] = bhh[o];
    }
}

__global__ void k_split_wct() {
    int idx = blockIdx.x * blockDim.x + threadIdx.x;
    if (idx >= G3D * Dd / 2) return;
    float2 v = ((const float2*)d_Wct)[idx];
    __nv_bfloat162 h, l;
    split2(v.x, v.y, h, l);
    ((__nv_bfloat162*)d_Wcthi)[idx] = h;
    ((__nv_bfloat162*)d_Wctlo)[idx] = l;
}

// ---------------- mma.sync helpers --------------------------------------------
__device__ __forceinline__ uint32_t cvta_s(const void* p) {
    return (uint32_t)__cvta_generic_to_shared(p);
}
__device__ __forceinline__ void ldsm_x4(uint32_t& r0, uint32_t& r1, uint32_t& r2, uint32_t& r3,
                                        uint32_t addr) {
    asm volatile("ldmatrix.sync.aligned.m8n8.x4.shared.b16 {%0,%1,%2,%3}, [%4];"
                 : "=r"(r0), "=r"(r1), "=r"(r2), "=r"(r3) : "r"(addr));
}
__device__ __forceinline__ void ldsm_x2(uint32_t& r0, uint32_t& r1, uint32_t addr) {
    asm volatile("ldmatrix.sync.aligned.m8n8.x2.shared.b16 {%0,%1}, [%2];"
                 : "=r"(r0), "=r"(r1) : "r"(addr));
}
__device__ __forceinline__ void mma_bf16(float* d, const uint32_t* a, const uint32_t* b) {
    asm volatile(
        "mma.sync.aligned.m16n8k16.row.col.f32.bf16.bf16.f32 "
        "{%0,%1,%2,%3}, {%4,%5,%6,%7}, {%8,%9}, {%0,%1,%2,%3};"
        : "+f"(d[0]), "+f"(d[1]), "+f"(d[2]), "+f"(d[3])
        : "r"(a[0]), "r"(a[1]), "r"(a[2]), "r"(a[3]), "r"(b[0]), "r"(b[1]));
}
#define CP16(dst, src) \
    asm volatile("cp.async.cg.shared.global [%0], [%1], 16;" :: "r"(dst), "l"(src))
#define CP_COMMIT() asm volatile("cp.async.commit_group;" ::: "memory")

#define SPAD 40

// ---------------- pre-split bf16 GEMM (128x128x32) — used for Wct only -------
#define ARR_BYTES (128 * SPAD * 2)
#define STAGE_BYTES (4 * ARR_BYTES)
#define GEMM_SMEM (2 * STAGE_BYTES)

__global__ __launch_bounds__(256, 2) void gemm_pre(
    const __nv_bfloat16* __restrict__ Ahi, const __nv_bfloat16* __restrict__ Alo,
    const __nv_bfloat16* __restrict__ Bhi, const __nv_bfloat16* __restrict__ Blo,
    float* __restrict__ C, const float* __restrict__ bias,
    int N, int K)
{
    extern __shared__ char smem[];
    const uint32_t sb = cvta_s(smem);
    const int t    = threadIdx.x;
    const int wid  = t >> 5;
    const int lane = t & 31;
    const int wm   = wid >> 2;
    const int wn   = wid & 3;
    const int m0   = blockIdx.y * 128;
    const int n0   = blockIdx.x * 128;
    const int lrow = t >> 2;
    const int lc4  = t & 3;

    float acc[4][4][4];
    #pragma unroll
    for (int mf = 0; mf < 4; mf++)
        #pragma unroll
        for (int nf = 0; nf < 4; nf++)
            #pragma unroll
            for (int j = 0; j < 4; j++) acc[mf][nf][j] = 0.0f;

    const int nchunks = K >> 5;

    auto load_stage = [&](int kc, int s) {
        uint32_t base = sb + s * STAGE_BYTES;
        #pragma unroll
        for (int i = 0; i < 2; i++) {
            int row = lrow + i * 64;
            uint32_t doff = (uint32_t)(row * (SPAD * 2) + lc4 * 16);
            size_t asrc = (size_t)(m0 + row) * K + kc * 32 + lc4 * 8;
            size_t bsrc = (size_t)(n0 + row) * K + kc * 32 + lc4 * 8;
            CP16(base + 0 * ARR_BYTES + doff, Ahi + asrc);
            CP16(base + 1 * ARR_BYTES + doff, Alo + asrc);
            CP16(base + 2 * ARR_BYTES + doff, Bhi + bsrc);
            CP16(base + 3 * ARR_BYTES + doff, Blo + bsrc);
        }
        CP_COMMIT();
    };

    load_stage(0, 0);

    for (int kc = 0; kc < nchunks; kc++) {
        const int s = kc & 1;
        if (kc + 1 < nchunks) {
            load_stage(kc + 1, s ^ 1);
            asm volatile("cp.async.wait_group 1;" ::: "memory");
        } else {
            asm volatile("cp.async.wait_group 0;" ::: "memory");
        }
        __syncthreads();

        const uint32_t base = sb + s * STAGE_BYTES;
        #pragma unroll
        for (int ks = 0; ks < 2; ks++) {
            const int k0 = ks * 16;
            uint32_t ahi[4][4], alo[4][4], bhi[4][2], blo[4][2];
            #pragma unroll
            for (int mf = 0; mf < 4; mf++) {
                int arow = wm * 64 + mf * 16 + (lane & 15);
                int acol = k0 + ((lane >> 4) & 1) * 8;
                uint32_t ao = (uint32_t)((arow * SPAD + acol) * 2);
                ldsm_x4(ahi[mf][0], ahi[mf][1], ahi[mf][2], ahi[mf][3], base + 0 * ARR_BYTES + ao);
                ldsm_x4(alo[mf][0], alo[mf][1], alo[mf][2], alo[mf][3], base + 1 * ARR_BYTES + ao);
            }
            #pragma unroll
            for (int nf = 0; nf < 4; nf++) {
                int brow = wn * 32 + nf * 8 + (lane & 7);
                int bcol = k0 + ((lane >> 3) & 1) * 8;
                uint32_t bo = (uint32_t)((brow * SPAD + bcol) * 2);
                ldsm_x2(bhi[nf][0], bhi[nf][1], base + 2 * ARR_BYTES + bo);
                ldsm_x2(blo[nf][0], blo[nf][1], base + 3 * ARR_BYTES + bo);
            }
            #pragma unroll
            for (int mf = 0; mf < 4; mf++)
                #pragma unroll
                for (int nf = 0; nf < 4; nf++) {
                    mma_bf16(acc[mf][nf], ahi[mf], bhi[nf]);
                    mma_bf16(acc[mf][nf], alo[mf], bhi[nf]);
                    mma_bf16(acc[mf][nf], ahi[mf], blo[nf]);
                }
        }
        __syncthreads();
    }

    const int erow = (lane >> 2);
    const int ecol = (lane & 3) * 2;
    #pragma unroll
    for (int mf = 0; mf < 4; mf++) {
        #pragma unroll
        for (int nf = 0; nf < 4; nf++) {
            int r0 = m0 + wm * 64 + mf * 16 + erow;
            int c0 = n0 + wn * 32 + nf * 8 + ecol;
            float b0 = 0.f, b1 = 0.f;
            if (bias) { b0 = bias[c0]; b1 = bias[c0 + 1]; }
            float2 v0 = make_float2(acc[mf][nf][0] + b0, acc[mf][nf][1] + b1);
            float2 v1 = make_float2(acc[mf][nf][2] + b0, acc[mf][nf][3] + b1);
            *(float2*)(C + (size_t)r0 * N + c0)       = v0;
            *(float2*)(C + (size_t)(r0 + 8) * N + c0) = v1;
        }
    }
}

// ---------------- mega-fused: gi GEMM + gh GEMM + GRU ------------------------
// Tile 128x96. Two simultaneous sub-GEMMs:
//   gi = aggx @ Wct^T   (A1 = agghi/agglo, B1 = Wcthi/Wctlo)
//   gh = x    @ Whh^T   (A2 = xhi/xlo,     B2 = Whhphi/Whhplo)
// then GRU epilogue -> out. All B rows permuted so a 96-col tile = 32 feats x 3 gates.
#define FA_BYTES (128 * SPAD * 2)   // 10240
#define FB_BYTES (96 * SPAD * 2)    // 7680
#define F_A1H 0
#define F_A1L (1 * FA_BYTES)
#define F_A2H (2 * FA_BYTES)
#define F_A2L (3 * FA_BYTES)
#define F_B1H (4 * FA_BYTES)
#define F_B1L (4 * FA_BYTES + 1 * FB_BYTES)
#define F_B2H (4 * FA_BYTES + 2 * FB_BYTES)
#define F_B2L (4 * FA_BYTES + 3 * FB_BYTES)
#define F_STAGE (4 * FA_BYTES + 4 * FB_BYTES)   // 71680
#define FUSE_SMEM (2 * F_STAGE)                 // 143360

__device__ __forceinline__ float sigmoidf_(float x) {
    return 1.0f / (1.0f + __expf(-x));
}

__global__ __launch_bounds__(256, 1) void gemm2_gru(
    const __nv_bfloat16* __restrict__ A1hi, const __nv_bfloat16* __restrict__ A1lo,
    const __nv_bfloat16* __restrict__ A2hi, const __nv_bfloat16* __restrict__ A2lo,
    const __nv_bfloat16* __restrict__ B1hi, const __nv_bfloat16* __restrict__ B1lo,
    const __nv_bfloat16* __restrict__ B2hi, const __nv_bfloat16* __restrict__ B2lo,
    const float* __restrict__ bihp, const float* __restrict__ bhhp,
    const float* __restrict__ x, const int* __restrict__ mask,
    float* __restrict__ out, int K)
{
    extern __shared__ char smem[];
    const uint32_t sb = cvta_s(smem);
    const int t    = threadIdx.x;
    const int wid  = t >> 5;
    const int lane = t & 31;
    const int wm   = wid >> 2;        // 0..1
    const int wn   = wid & 3;         // 0..3 (24-col slices)
    const int m0   = blockIdx.y * 128;
    const int n0   = blockIdx.x * 96;
    const int lrow = t >> 2;
    const int lc4  = t & 3;

    float acci[4][3][4];   // gi accumulators
    float acch[4][3][4];   // gh accumulators
    #pragma unroll
    for (int mf = 0; mf < 4; mf++)
        #pragma unroll
        for (int nf = 0; nf < 3; nf++)
            #pragma unroll
            for (int j = 0; j < 4; j++) { acci[mf][nf][j] = 0.0f; acch[mf][nf][j] = 0.0f; }

    const int nchunks = K >> 5;   // 8

    auto load_stage = [&](int kc, int s) {
        uint32_t base = sb + s * F_STAGE;
        #pragma unroll
        for (int i = 0; i < 2; i++) {
            int row = lrow + i * 64;
            uint32_t doff = (uint32_t)(row * (SPAD * 2) + lc4 * 16);
            size_t asrc = (size_t)(m0 + row) * K + kc * 32 + lc4 * 8;
            CP16(base + F_A1H + doff, A1hi + asrc);
            CP16(base + F_A1L + doff, A1lo + asrc);
            CP16(base + F_A2H + doff, A2hi + asrc);
            CP16(base + F_A2L + doff, A2lo + asrc);
        }
        {   // B: 96 rows x 4 chunks = 384 per array
            int c = t;
            int row = c >> 2, c4 = c & 3;
            uint32_t doff = (uint32_t)(row * (SPAD * 2) + c4 * 16);
            size_t bsrc = (size_t)(n0 + row) * K + kc * 32 + c4 * 8;
            CP16(base + F_B1H + doff, B1hi + bsrc);
            CP16(base + F_B1L + doff, B1lo + bsrc);
            CP16(base + F_B2H + doff, B2hi + bsrc);
            CP16(base + F_B2L + doff, B2lo + bsrc);
            if (t < 128) {
                c = t + 256;
                row = c >> 2; c4 = c & 3;
                doff = (uint32_t)(row * (SPAD * 2) + c4 * 16);
                bsrc = (size_t)(n0 + row) * K + kc * 32 + c4 * 8;
                CP16(base + F_B1H + doff, B1hi + bsrc);
                CP16(base + F_B1L + doff, B1lo + bsrc);
                CP16(base + F_B2H + doff, B2hi + bsrc);
                CP16(base + F_B2L + doff, B2lo + bsrc);
            }
        }
        CP_COMMIT();
    };

    load_stage(0, 0);

    for (int kc = 0; kc < nchunks; kc++) {
        const int s = kc & 1;
        if (kc + 1 < nchunks) {
            load_stage(kc + 1, s ^ 1);
            asm volatile("cp.async.wait_group 1;" ::: "memory");
        } else {
            asm volatile("cp.async.wait_group 0;" ::: "memory");
        }
        __syncthreads();

        const uint32_t base = sb + s * F_STAGE;
        #pragma unroll
        for (int ks = 0; ks < 2; ks++) {
            const int k0 = ks * 16;
            const int arow = wm * 64 + (lane & 15);
            const int acol = k0 + ((lane >> 4) & 1) * 8;
            const int brow = wn * 24 + (lane & 7);
            const int bcol = k0 + ((lane >> 3) & 1) * 8;

            {   // sub-GEMM 1: gi
                uint32_t ahi[4][4], alo[4][4], bhi[3][2], blo[3][2];
                #pragma unroll
                for (int mf = 0; mf < 4; mf++) {
                    uint32_t ao = (uint32_t)(((arow + mf * 16) * SPAD + acol) * 2);
                    ldsm_x4(ahi[mf][0], ahi[mf][1], ahi[mf][2], ahi[mf][3], base + F_A1H + ao);
                    ldsm_x4(alo[mf][0], alo[mf][1], alo[mf][2], alo[mf][3], base + F_A1L + ao);
                }
                #pragma unroll
                for (int nf = 0; nf < 3; nf++) {
                    uint32_t bo = (uint32_t)(((brow + nf * 8) * SPAD + bcol) * 2);
                    ldsm_x2(bhi[nf][0], bhi[nf][1], base + F_B1H + bo);
                    ldsm_x2(blo[nf][0], blo[nf][1], base + F_B1L + bo);
                }
                #pragma unroll
                for (int mf = 0; mf < 4; mf++)
                    #pragma unroll
                    for (int nf = 0; nf < 3; nf++) {
                        mma_bf16(acci[mf][nf], ahi[mf], bhi[nf]);
                        mma_bf16(acci[mf][nf], alo[mf], bhi[nf]);
                        mma_bf16(acci[mf][nf], ahi[mf], blo[nf]);
                    }
            }
            {   // sub-GEMM 2: gh
                uint32_t ahi[4][4], alo[4][4], bhi[3][2], blo[3][2];
                #pragma unroll
                for (int mf = 0; mf < 4; mf++) {
                    uint32_t ao = (uint32_t)(((arow + mf * 16) * SPAD + acol) * 2);
                    ldsm_x4(ahi[mf][0], ahi[mf][1], ahi[mf][2], ahi[mf][3], base + F_A2H + ao);
                    ldsm_x4(alo[mf][0], alo[mf][1], alo[mf][2], alo[mf][3], base + F_A2L + ao);
                }
                #pragma unroll
                for (int nf = 0; nf < 3; nf++) {
                    uint32_t bo = (uint32_t)(((brow + nf * 8) * SPAD + bcol) * 2);
                    ldsm_x2(bhi[nf][0], bhi[nf][1], base + F_B2H + bo);
                    ldsm_x2(blo[nf][0], blo[nf][1], base + F_B2L + bo);
                }
                #pragma unroll
                for (int mf = 0; mf < 4; mf++)
                    #pragma unroll
                    for (int nf = 0; nf < 3; nf++) {
                        mma_bf16(acch[mf][nf], ahi[mf], bhi[nf]);
                        mma_bf16(acch[mf][nf], alo[mf], bhi[nf]);
                        mma_bf16(acch[mf][nf], ahi[mf], blo[nf]);
                    }
            }
        }
        __syncthreads();
    }

    // phase 1: fragments -> smem tiles gis[128][100], ghs[128][100]
    float* gis = (float*)smem;
    float* ghs = (float*)smem + 128 * 100;
    const int erow = (lane >> 2);
    const int ecol = (lane & 3) * 2;
    #pragma unroll
    for (int mf = 0; mf < 4; mf++) {
        #pragma unroll
        for (int nf = 0; nf < 3; nf++) {
            int r0 = wm * 64 + mf * 16 + erow;
            int c0 = wn * 24 + nf * 8 + ecol;
            *(float2*)&gis[r0 * 100 + c0]       = make_float2(acci[mf][nf][0], acci[mf][nf][1]);
            *(float2*)&gis[(r0 + 8) * 100 + c0] = make_float2(acci[mf][nf][2], acci[mf][nf][3]);
            *(float2*)&ghs[r0 * 100 + c0]       = make_float2(acch[mf][nf][0], acch[mf][nf][1]);
            *(float2*)&ghs[(r0 + 8) * 100 + c0] = make_float2(acch[mf][nf][2], acch[mf][nf][3]);
        }
    }
    __syncthreads();

    // phase 2: GRU. thread t: feature f = t&31; rows r = (t>>5)*16 + 0..15
    const int f    = t & 31;
    const int rg0  = (t >> 5) * 16;
    const int fglob = blockIdx.x * 32 + f;
    const float bi_r = bihp[n0 + f];
    const float bi_z = bihp[n0 + 32 + f];
    const float bi_n = bihp[n0 + 64 + f];
    const float bh_r = bhhp[n0 + f];
    const float bh_z = bhhp[n0 + 32 + f];
    const float bh_n = bhhp[n0 + 64 + f];

    #pragma unroll
    for (int i = 0; i < 16; i++) {
        int r = rg0 + i;
        int row_g = m0 + r;
        float valid = (mask[row_g] > 0) ? 1.0f : 0.0f;
        float gi_r = gis[r * 100 + f]      + bi_r;
        float gi_z = gis[r * 100 + 32 + f] + bi_z;
        float gi_n = gis[r * 100 + 64 + f] + bi_n;
        float gh_r = ghs[r * 100 + f]      + bh_r;
        float gh_z = ghs[r * 100 + 32 + f] + bh_z;
        float gh_n = ghs[r * 100 + 64 + f] + bh_n;
        float xv = x[(size_t)row_g * Dd + fglob];
        float rr = sigmoidf_(gi_r + gh_r);
        float zz = sigmoidf_(gi_z + gh_z);
        float nn = tanhf(gi_n + rr * gh_n);
        out[(size_t)row_g * Dd + fglob] = ((1.0f - zz) * nn + zz * xv) * valid;
    }
}

// ---------------- aggregation on x (writes split bf16) -----------------------
__global__ void k_aggregate(const float* __restrict__ x) {
    int node = blockIdx.x;
    int t = threadIdx.x;
    int start = d_rowptr[node];
    int end   = d_rowptr[node + 1];
    int bBase = (node >> 12) << 12;
    float4 acc = make_float4(0.f, 0.f, 0.f, 0.f);
    for (int j = start; j < end; j++) {
        int src = d_esrc[j];
        float w = d_eww[j];
        float4 xv = __ldg((const float4*)&x[(size_t)(bBase + src) * Dd] + t);
        acc.x += w * xv.x; acc.y += w * xv.y; acc.z += w * xv.z; acc.w += w * xv.w;
    }
    __nv_bfloat162 h0, l0, h1, l1;
    split2(acc.x, acc.y, h0, l0);
    split2(acc.z, acc.w, h1, l1);
    size_t o = (size_t)node * (Dd / 2) + t * 2;
    ((__nv_bfloat162*)d_agghi)[o]     = h0;
    ((__nv_bfloat162*)d_agghi)[o + 1] = h1;
    ((__nv_bfloat162*)d_agglo)[o]     = l0;
    ((__nv_bfloat162*)d_agglo)[o + 1] = l1;
}

// ---------------- launch ------------------------------------------------------
extern "C" void kernel_launch(void* const* d_in, const int* in_sizes, int n_in,
                              void* d_out, int out_size) {
    const float* x    = (const float*)d_in[0];
    const int*   ei   = (const int*)  d_in[1];
    const float* ew   = (const float*)d_in[2];
    const int*   mask = (const int*)  d_in[3];
    const float* W    = (const float*)d_in[4];
    const float* Wih  = (const float*)d_in[5];
    const float* Whh  = (const float*)d_in[6];
    const float* bih  = (const float*)d_in[7];
    const float* bhh  = (const float*)d_in[8];
    float* out = (float*)d_out;

    float *p_wct, *p_bihp, *p_bhhp;
    __nv_bfloat16 *p_xhi, *p_xlo, *p_agghi, *p_agglo;
    __nv_bfloat16 *p_whi, *p_wlo, *p_wihphi, *p_wihplo, *p_whhphi, *p_whhplo, *p_wcthi, *p_wctlo;
    cudaGetSymbolAddress((void**)&p_wct,    d_Wct);
    cudaGetSymbolAddress((void**)&p_bihp,   d_bihp);
    cudaGetSymbolAddress((void**)&p_bhhp,   d_bhhp);
    cudaGetSymbolAddress((void**)&p_xhi,    d_xhi);
    cudaGetSymbolAddress((void**)&p_xlo,    d_xlo);
    cudaGetSymbolAddress((void**)&p_agghi,  d_agghi);
    cudaGetSymbolAddress((void**)&p_agglo,  d_agglo);
    cudaGetSymbolAddress((void**)&p_whi,    d_Whi);
    cudaGetSymbolAddress((void**)&p_wlo,    d_Wlo);
    cudaGetSymbolAddress((void**)&p_wihphi, d_Wihphi);
    cudaGetSymbolAddress((void**)&p_wihplo, d_Wihplo);
    cudaGetSymbolAddress((void**)&p_whhphi, d_Whhphi);
    cudaGetSymbolAddress((void**)&p_whhplo, d_Whhplo);
    cudaGetSymbolAddress((void**)&p_wcthi,  d_Wcthi);
    cudaGetSymbolAddress((void**)&p_wctlo,  d_Wctlo);

    cudaFuncSetAttribute(gemm_pre, cudaFuncAttributeMaxDynamicSharedMemorySize, GEMM_SMEM);
    cudaFuncSetAttribute(gemm2_gru, cudaFuncAttributeMaxDynamicSharedMemorySize, FUSE_SMEM);

    // CSR build
    k_zero<<<(NODES + 255) / 256, 256>>>();
    k_count<<<EDGES / 256, 256>>>(ei, mask);
    k_scan<<<1, 1024>>>();
    k_fill<<<EDGES / 256, 256>>>(ei, mask, ew);

    // splits + permutes
    k_split_x<<<(NODES * Dd / 2 + 255) / 256, 256>>>(x);
    k_split_W<<<(Dd * Dd / 2 + 255) / 256, 256>>>(W);
    k_permsplit<<<(G3D * Dd / 2 + 255) / 256, 256>>>(Wih, Whh, bih, bhh);

    // Wct = Wih(perm) @ W^T : [768,256], rows already permuted
    {
        dim3 grid(Dd / 128, G3D / 128);     // (2, 6)
        gemm_pre<<<grid, 256, GEMM_SMEM>>>(p_wihphi, p_wihplo, p_whi, p_wlo, p_wct, nullptr, Dd, Dd);
    }
    k_split_wct<<<(G3D * Dd / 2 + 255) / 256, 256>>>();

    // aggx = segment_sum(x[u] * w, v), split bf16
    k_aggregate<<<NODES, 64>>>(x);

    // fused: gi = aggx @ Wct^T, gh = x @ Whh^T, GRU -> out
    {
        dim3 grid(G3D / 96, NODES / 128);   // (8, 256)
        gemm2_gru<<<grid, 256, FUSE_SMEM>>>(p_agghi, p_agglo, p_xhi, p_xlo,
                                            p_wcthi, p_wctlo, p_whhphi, p_whhplo,
                                            p_bihp, p_bhhp, x, mask, out, Dd);
    }
}

// round 7
// speedup vs baseline: 1.2935x; 1.2935x over previous
#include <cuda_runtime.h>
#include <cuda_fp16.h>
#include <math.h>
#include <cstdint>

#define Bb 8
#define Nn 4096
#define Dd 256
#define Ee 65536
#define NODES (Bb * Nn)        // 32768
#define EDGES (Bb * Ee)        // 524288
#define G3D   (3 * Dd)         // 768

// ---------------- scratch (static device globals; no allocation) -------------
__device__ float d_gi[NODES * G3D];                // permuted-col layout
__device__ float d_Wct[G3D * Dd];                  // (Wih @ W^T), permuted rows (fp32)
__device__ __half d_xhi[NODES * Dd];
__device__ __half d_xlo[NODES * Dd];
__device__ __half d_agghi[NODES * Dd];
__device__ __half d_agglo[NODES * Dd];
__device__ __half d_Whi[Dd * Dd];                  // W split (for accurate Wct)
__device__ __half d_Wlo[Dd * Dd];
__device__ __half d_Wihphi[G3D * Dd];              // Wih, rows permuted, split
__device__ __half d_Wihplo[G3D * Dd];
__device__ __half d_Whhp[G3D * Dd];                // Whh, rows permuted, single fp16
__device__ __half d_Wcth[G3D * Dd];                // Wct rounded to fp16
__device__ float d_bihp[G3D];
__device__ float d_bhhp[G3D];
__device__ int   d_counts[NODES];
__device__ int   d_cursor[NODES];
__device__ int   d_rowptr[NODES + 1];
__device__ int   d_esrc[EDGES];
__device__ float d_eww[EDGES];

// permutation: orig row o = g*256+d  ->  o' = (d>>5)*96 + g*32 + (d&31)

// ---------------- CSR construction -------------------------------------------
__global__ void k_zero() {
    int i = blockIdx.x * blockDim.x + threadIdx.x;
    if (i < NODES) { d_counts[i] = 0; d_cursor[i] = 0; }
}

__global__ void k_count(const int* __restrict__ ei, const int* __restrict__ mask) {
    int idx = blockIdx.x * blockDim.x + threadIdx.x;
    if (idx >= EDGES) return;
    int b = idx >> 16;
    int e = idx & (Ee - 1);
    int u = ei[((b << 1) + 0) * Ee + e];
    int v = ei[((b << 1) + 1) * Ee + e];
    if (mask[(b << 12) + u] > 0 && mask[(b << 12) + v] > 0)
        atomicAdd(&d_counts[(b << 12) + v], 1);
}

__global__ void k_scan() {
    __shared__ int sums[1024];
    int t = threadIdx.x;
    int base = t * 32;
    int s = 0;
    #pragma unroll
    for (int i = 0; i < 32; i++) s += d_counts[base + i];
    sums[t] = s;
    __syncthreads();
    for (int off = 1; off < 1024; off <<= 1) {
        int v = (t >= off) ? sums[t - off] : 0;
        __syncthreads();
        sums[t] += v;
        __syncthreads();
    }
    int run = (t == 0) ? 0 : sums[t - 1];
    #pragma unroll
    for (int i = 0; i < 32; i++) {
        d_rowptr[base + i] = run;
        run += d_counts[base + i];
    }
    if (t == 1023) d_rowptr[NODES] = sums[1023];
}

__global__ void k_fill(const int* __restrict__ ei, const int* __restrict__ mask,
                       const float* __restrict__ ew) {
    int idx = blockIdx.x * blockDim.x + threadIdx.x;
    if (idx >= EDGES) return;
    int b = idx >> 16;
    int e = idx & (Ee - 1);
    int u = ei[((b << 1) + 0) * Ee + e];
    int v = ei[((b << 1) + 1) * Ee + e];
    if (mask[(b << 12) + u] > 0 && mask[(b << 12) + v] > 0) {
        int node = (b << 12) + v;
        int pos = d_rowptr[node] + atomicAdd(&d_cursor[node], 1);
        d_esrc[pos] = u;
        d_eww[pos]  = ew[idx];
    }
}

// ---------------- split helpers -----------------------------------------------
__device__ __forceinline__ void split2h(float a, float b, __half2& hi, __half2& lo) {
    hi = __floats2half2_rn(a, b);
    lo = __floats2half2_rn(a - __low2float(hi), b - __high2float(hi));
}

__global__ void k_split_x(const float* __restrict__ x) {
    int idx = blockIdx.x * blockDim.x + threadIdx.x;
    if (idx >= NODES * Dd / 2) return;
    float2 v = ((const float2*)x)[idx];
    __half2 h, l;
    split2h(v.x, v.y, h, l);
    ((__half2*)d_xhi)[idx] = h;
    ((__half2*)d_xlo)[idx] = l;
}

__global__ void k_split_W(const float* __restrict__ W) {
    int idx = blockIdx.x * blockDim.x + threadIdx.x;
    if (idx >= Dd * Dd / 2) return;
    float2 v = ((const float2*)W)[idx];
    __half2 h, l;
    split2h(v.x, v.y, h, l);
    ((__half2*)d_Whi)[idx] = h;
    ((__half2*)d_Wlo)[idx] = l;
}

// permuted-row: Wih split (A of Wct GEMM), Whh single fp16 (B of gh GEMM), biases
__global__ void k_permsplit(const float* __restrict__ wih, const float* __restrict__ whh,
                            const float* __restrict__ bih, const float* __restrict__ bhh) {
    int idx = blockIdx.x * blockDim.x + threadIdx.x;   // G3D * Dd/2
    if (idx >= G3D * Dd / 2) return;
    int o    = idx / (Dd / 2);
    int col2 = idx - o * (Dd / 2);
    int g = o >> 8, d = o & 255;
    int op = (d >> 5) * 96 + g * 32 + (d & 31);
    size_t dst = (size_t)op * (Dd / 2) + col2;
    float2 a = ((const float2*)wih)[idx];
    __half2 h, l;
    split2h(a.x, a.y, h, l);
    ((__half2*)d_Wihphi)[dst] = h;
    ((__half2*)d_Wihplo)[dst] = l;
    float2 b = ((const float2*)whh)[idx];
    ((__half2*)d_Whhp)[dst] = __floats2half2_rn(b.x, b.y);
    if (col2 == 0) {
        d_bihp[op] = bih[o];
        d_bhhp[op] = bhh[o];
    }
}

__global__ void k_round_wct() {
    int idx = blockIdx.x * blockDim.x + threadIdx.x;
    if (idx >= G3D * Dd / 2) return;
    float2 v = ((const float2*)d_Wct)[idx];
    ((__half2*)d_Wcth)[idx] = __floats2half2_rn(v.x, v.y);
}

// ---------------- mma.sync helpers --------------------------------------------
__device__ __forceinline__ uint32_t cvta_s(const void* p) {
    return (uint32_t)__cvta_generic_to_shared(p);
}
__device__ __forceinline__ void ldsm_x4(uint32_t& r0, uint32_t& r1, uint32_t& r2, uint32_t& r3,
                                        uint32_t addr) {
    asm volatile("ldmatrix.sync.aligned.m8n8.x4.shared.b16 {%0,%1,%2,%3}, [%4];"
                 : "=r"(r0), "=r"(r1), "=r"(r2), "=r"(r3) : "r"(addr));
}
__device__ __forceinline__ void ldsm_x2(uint32_t& r0, uint32_t& r1, uint32_t addr) {
    asm volatile("ldmatrix.sync.aligned.m8n8.x2.shared.b16 {%0,%1}, [%2];"
                 : "=r"(r0), "=r"(r1) : "r"(addr));
}
__device__ __forceinline__ void mma_f16(float* d, const uint32_t* a, const uint32_t* b) {
    asm volatile(
        "mma.sync.aligned.m16n8k16.row.col.f32.f16.f16.f32 "
        "{%0,%1,%2,%3}, {%4,%5,%6,%7}, {%8,%9}, {%0,%1,%2,%3};"
        : "+f"(d[0]), "+f"(d[1]), "+f"(d[2]), "+f"(d[3])
        : "r"(a[0]), "r"(a[1]), "r"(a[2]), "r"(a[3]), "r"(b[0]), "r"(b[1]));
}
#define CP16(dst, src) \
    asm volatile("cp.async.cg.shared.global [%0], [%1], 16;" :: "r"(dst), "l"(src))
#define CP_COMMIT() asm volatile("cp.async.commit_group;" ::: "memory")

#define SPAD 40
#define ARRB (128 * SPAD * 2)   // 10240 bytes per 128xBK half array

// ---------------- fp16 split GEMM (128x128x32): C = A*B^T (+bias) -------------
// A exact-split (Ahi+Alo); B rounded (Bhi), optional Blo for 3-product accuracy.
template<bool BLO>
__global__ __launch_bounds__(256, 2) void gemm_h(
    const __half* __restrict__ Ahi, const __half* __restrict__ Alo,
    const __half* __restrict__ Bhi, const __half* __restrict__ Blo,
    float* __restrict__ C, const float* __restrict__ bias,
    int N, int K)
{
    constexpr int NARR  = BLO ? 4 : 3;
    constexpr int STAGE = NARR * ARRB;
    extern __shared__ char smem[];
    const uint32_t sb = cvta_s(smem);
    const int t    = threadIdx.x;
    const int wid  = t >> 5;
    const int lane = t & 31;
    const int wm   = wid >> 2;
    const int wn   = wid & 3;
    const int m0   = blockIdx.y * 128;
    const int n0   = blockIdx.x * 128;
    const int lrow = t >> 2;
    const int lc4  = t & 3;

    float acc[4][4][4];
    #pragma unroll
    for (int mf = 0; mf < 4; mf++)
        #pragma unroll
        for (int nf = 0; nf < 4; nf++)
            #pragma unroll
            for (int j = 0; j < 4; j++) acc[mf][nf][j] = 0.0f;

    const int nchunks = K >> 5;

    auto load_stage = [&](int kc, int s) {
        uint32_t base = sb + s * STAGE;
        #pragma unroll
        for (int i = 0; i < 2; i++) {
            int row = lrow + i * 64;
            uint32_t doff = (uint32_t)(row * (SPAD * 2) + lc4 * 16);
            size_t asrc = (size_t)(m0 + row) * K + kc * 32 + lc4 * 8;
            size_t bsrc = (size_t)(n0 + row) * K + kc * 32 + lc4 * 8;
            CP16(base + 0 * ARRB + doff, Ahi + asrc);
            CP16(base + 1 * ARRB + doff, Alo + asrc);
            CP16(base + 2 * ARRB + doff, Bhi + bsrc);
            if (BLO) CP16(base + 3 * ARRB + doff, Blo + bsrc);
        }
        CP_COMMIT();
    };

    load_stage(0, 0);

    for (int kc = 0; kc < nchunks; kc++) {
        const int s = kc & 1;
        if (kc + 1 < nchunks) {
            load_stage(kc + 1, s ^ 1);
            asm volatile("cp.async.wait_group 1;" ::: "memory");
        } else {
            asm volatile("cp.async.wait_group 0;" ::: "memory");
        }
        __syncthreads();

        const uint32_t base = sb + s * STAGE;
        #pragma unroll
        for (int ks = 0; ks < 2; ks++) {
            const int k0 = ks * 16;
            uint32_t ahi[4][4], alo[4][4], bhi[4][2], blo[4][2];
            #pragma unroll
            for (int mf = 0; mf < 4; mf++) {
                int arow = wm * 64 + mf * 16 + (lane & 15);
                int acol = k0 + ((lane >> 4) & 1) * 8;
                uint32_t ao = (uint32_t)((arow * SPAD + acol) * 2);
                ldsm_x4(ahi[mf][0], ahi[mf][1], ahi[mf][2], ahi[mf][3], base + 0 * ARRB + ao);
                ldsm_x4(alo[mf][0], alo[mf][1], alo[mf][2], alo[mf][3], base + 1 * ARRB + ao);
            }
            #pragma unroll
            for (int nf = 0; nf < 4; nf++) {
                int brow = wn * 32 + nf * 8 + (lane & 7);
                int bcol = k0 + ((lane >> 3) & 1) * 8;
                uint32_t bo = (uint32_t)((brow * SPAD + bcol) * 2);
                ldsm_x2(bhi[nf][0], bhi[nf][1], base + 2 * ARRB + bo);
                if (BLO) ldsm_x2(blo[nf][0], blo[nf][1], base + 3 * ARRB + bo);
            }
            #pragma unroll
            for (int mf = 0; mf < 4; mf++)
                #pragma unroll
                for (int nf = 0; nf < 4; nf++) {
                    mma_f16(acc[mf][nf], ahi[mf], bhi[nf]);
                    mma_f16(acc[mf][nf], alo[mf], bhi[nf]);
                    if (BLO) mma_f16(acc[mf][nf], ahi[mf], blo[nf]);
                }
        }
        __syncthreads();
    }

    const int erow = (lane >> 2);
    const int ecol = (lane & 3) * 2;
    #pragma unroll
    for (int mf = 0; mf < 4; mf++) {
        #pragma unroll
        for (int nf = 0; nf < 4; nf++) {
            int r0 = m0 + wm * 64 + mf * 16 + erow;
            int c0 = n0 + wn * 32 + nf * 8 + ecol;
            float b0 = 0.f, b1 = 0.f;
            if (bias) { b0 = bias[c0]; b1 = bias[c0 + 1]; }
            float2 v0 = make_float2(acc[mf][nf][0] + b0, acc[mf][nf][1] + b1);
            float2 v1 = make_float2(acc[mf][nf][2] + b0, acc[mf][nf][3] + b1);
            *(float2*)(C + (size_t)r0 * N + c0)       = v0;
            *(float2*)(C + (size_t)(r0 + 8) * N + c0) = v1;
        }
    }
}

// ---------------- fused gh GEMM (128x96x32) + GRU epilogue -------------------
// A = x split; B = Whh permuted single fp16. 96-col tile = 32 feats x 3 gates.
#define FB_BYTES (96 * SPAD * 2)                  // 7680
#define F_A2H 0
#define F_A2L ARRB
#define F_B2  (2 * ARRB)
#define F_STAGE (2 * ARRB + FB_BYTES)             // 28160
#define FUSE_SMEM (2 * F_STAGE)                   // 56320 (>= 128*100*4=51200)

__device__ __forceinline__ float sigmoidf_(float x) {
    return 1.0f / (1.0f + __expf(-x));
}

__global__ __launch_bounds__(256, 2) void gemm_gru(
    const __half* __restrict__ Ahi, const __half* __restrict__ Alo,
    const __half* __restrict__ Bh,
    const float* __restrict__ gi, const float* __restrict__ bhhp,
    const float* __restrict__ x, const int* __restrict__ mask,
    float* __restrict__ out, int K)
{
    extern __shared__ char smem[];
    const uint32_t sb = cvta_s(smem);
    const int t    = threadIdx.x;
    const int wid  = t >> 5;
    const int lane = t & 31;
    const int wm   = wid >> 2;        // 0..1
    const int wn   = wid & 3;         // 0..3 (24-col slices)
    const int m0   = blockIdx.y * 128;
    const int n0   = blockIdx.x * 96;
    const int lrow = t >> 2;
    const int lc4  = t & 3;

    float acc[4][3][4];
    #pragma unroll
    for (int mf = 0; mf < 4; mf++)
        #pragma unroll
        for (int nf = 0; nf < 3; nf++)
            #pragma unroll
            for (int j = 0; j < 4; j++) acc[mf][nf][j] = 0.0f;

    const int nchunks = K >> 5;

    auto load_stage = [&](int kc, int s) {
        uint32_t base = sb + s * F_STAGE;
        #pragma unroll
        for (int i = 0; i < 2; i++) {
            int row = lrow + i * 64;
            uint32_t doff = (uint32_t)(row * (SPAD * 2) + lc4 * 16);
            size_t asrc = (size_t)(m0 + row) * K + kc * 32 + lc4 * 8;
            CP16(base + F_A2H + doff, Ahi + asrc);
            CP16(base + F_A2L + doff, Alo + asrc);
        }
        {   // B: 96 rows x 4 chunks = 384
            int c = t;
            int row = c >> 2, c4 = c & 3;
            uint32_t doff = (uint32_t)(row * (SPAD * 2) + c4 * 16);
            size_t bsrc = (size_t)(n0 + row) * K + kc * 32 + c4 * 8;
            CP16(base + F_B2 + doff, Bh + bsrc);
            if (t < 128) {
                c = t + 256;
                row = c >> 2; c4 = c & 3;
                doff = (uint32_t)(row * (SPAD * 2) + c4 * 16);
                bsrc = (size_t)(n0 + row) * K + kc * 32 + c4 * 8;
                CP16(base + F_B2 + doff, Bh + bsrc);
            }
        }
        CP_COMMIT();
    };

    load_stage(0, 0);

    for (int kc = 0; kc < nchunks; kc++) {
        const int s = kc & 1;
        if (kc + 1 < nchunks) {
            load_stage(kc + 1, s ^ 1);
            asm volatile("cp.async.wait_group 1;" ::: "memory");
        } else {
            asm volatile("cp.async.wait_group 0;" ::: "memory");
        }
        __syncthreads();

        const uint32_t base = sb + s * F_STAGE;
        #pragma unroll
        for (int ks = 0; ks < 2; ks++) {
            const int k0 = ks * 16;
            uint32_t ahi[4][4], alo[4][4], bh[3][2];
            #pragma unroll
            for (int mf = 0; mf < 4; mf++) {
                int arow = wm * 64 + mf * 16 + (lane & 15);
                int acol = k0 + ((lane >> 4) & 1) * 8;
                uint32_t ao = (uint32_t)((arow * SPAD + acol) * 2);
                ldsm_x4(ahi[mf][0], ahi[mf][1], ahi[mf][2], ahi[mf][3], base + F_A2H + ao);
                ldsm_x4(alo[mf][0], alo[mf][1], alo[mf][2], alo[mf][3], base + F_A2L + ao);
            }
            #pragma unroll
            for (int nf = 0; nf < 3; nf++) {
                int brow = wn * 24 + nf * 8 + (lane & 7);
                int bcol = k0 + ((lane >> 3) & 1) * 8;
                uint32_t bo = (uint32_t)((brow * SPAD + bcol) * 2);
                ldsm_x2(bh[nf][0], bh[nf][1], base + F_B2 + bo);
            }
            #pragma unroll
            for (int mf = 0; mf < 4; mf++)
                #pragma unroll
                for (int nf = 0; nf < 3; nf++) {
                    mma_f16(acc[mf][nf], ahi[mf], bh[nf]);
                    mma_f16(acc[mf][nf], alo[mf], bh[nf]);
                }
        }
        __syncthreads();
    }

    // phase 1: fragments -> smem tile ghs[128][100]
    float* ghs = (float*)smem;
    const int erow = (lane >> 2);
    const int ecol = (lane & 3) * 2;
    #pragma unroll
    for (int mf = 0; mf < 4; mf++) {
        #pragma unroll
        for (int nf = 0; nf < 3; nf++) {
            int r0 = wm * 64 + mf * 16 + erow;
            int c0 = wn * 24 + nf * 8 + ecol;
            *(float2*)&ghs[r0 * 100 + c0]       = make_float2(acc[mf][nf][0], acc[mf][nf][1]);
            *(float2*)&ghs[(r0 + 8) * 100 + c0] = make_float2(acc[mf][nf][2], acc[mf][nf][3]);
        }
    }
    __syncthreads();

    // phase 2: GRU. thread t: feature f = t&31; rows r = (t>>5)*16 + 0..15
    const int f    = t & 31;
    const int rg0  = (t >> 5) * 16;
    const int fglob = blockIdx.x * 32 + f;
    const float bh_r = bhhp[n0 + f];
    const float bh_z = bhhp[n0 + 32 + f];
    const float bh_n = bhhp[n0 + 64 + f];

    #pragma unroll
    for (int i = 0; i < 16; i++) {
        int r = rg0 + i;
        int row_g = m0 + r;
        float valid = (mask[row_g] > 0) ? 1.0f : 0.0f;
        const float* gip = gi + (size_t)row_g * G3D + n0;
        float gi_r = gip[f];
        float gi_z = gip[32 + f];
        float gi_n = gip[64 + f];
        float gh_r = ghs[r * 100 + f]      + bh_r;
        float gh_z = ghs[r * 100 + 32 + f] + bh_z;
        float gh_n = ghs[r * 100 + 64 + f] + bh_n;
        float xv = x[(size_t)row_g * Dd + fglob];
        float rr = sigmoidf_(gi_r + gh_r);
        float zz = sigmoidf_(gi_z + gh_z);
        float nn = tanhf(gi_n + rr * gh_n);
        out[(size_t)row_g * Dd + fglob] = ((1.0f - zz) * nn + zz * xv) * valid;
    }
}

// ---------------- aggregation on x (writes split fp16) -----------------------
__global__ void k_aggregate(const float* __restrict__ x) {
    int node = blockIdx.x;
    int t = threadIdx.x;
    int start = d_rowptr[node];
    int end   = d_rowptr[node + 1];
    int bBase = (node >> 12) << 12;
    float4 acc = make_float4(0.f, 0.f, 0.f, 0.f);
    for (int j = start; j < end; j++) {
        int src = d_esrc[j];
        float w = d_eww[j];
        float4 xv = __ldg((const float4*)&x[(size_t)(bBase + src) * Dd] + t);
        acc.x += w * xv.x; acc.y += w * xv.y; acc.z += w * xv.z; acc.w += w * xv.w;
    }
    __half2 h0, l0, h1, l1;
    split2h(acc.x, acc.y, h0, l0);
    split2h(acc.z, acc.w, h1, l1);
    size_t o = (size_t)node * (Dd / 2) + t * 2;
    ((__half2*)d_agghi)[o]     = h0;
    ((__half2*)d_agghi)[o + 1] = h1;
    ((__half2*)d_agglo)[o]     = l0;
    ((__half2*)d_agglo)[o + 1] = l1;
}

// ---------------- launch ------------------------------------------------------
extern "C" void kernel_launch(void* const* d_in, const int* in_sizes, int n_in,
                              void* d_out, int out_size) {
    const float* x    = (const float*)d_in[0];
    const int*   ei   = (const int*)  d_in[1];
    const float* ew   = (const float*)d_in[2];
    const int*   mask = (const int*)  d_in[3];
    const float* W    = (const float*)d_in[4];
    const float* Wih  = (const float*)d_in[5];
    const float* Whh  = (const float*)d_in[6];
    const float* bih  = (const float*)d_in[7];
    const float* bhh  = (const float*)d_in[8];
    float* out = (float*)d_out;

    float *p_gi, *p_wct, *p_bihp, *p_bhhp;
    __half *p_xhi, *p_xlo, *p_agghi, *p_agglo;
    __half *p_whi, *p_wlo, *p_wihphi, *p_wihplo, *p_whhp, *p_wcth;
    cudaGetSymbolAddress((void**)&p_gi,     d_gi);
    cudaGetSymbolAddress((void**)&p_wct,    d_Wct);
    cudaGetSymbolAddress((void**)&p_bihp,   d_bihp);
    cudaGetSymbolAddress((void**)&p_bhhp,   d_bhhp);
    cudaGetSymbolAddress((void**)&p_xhi,    d_xhi);
    cudaGetSymbolAddress((void**)&p_xlo,    d_xlo);
    cudaGetSymbolAddress((void**)&p_agghi,  d_agghi);
    cudaGetSymbolAddress((void**)&p_agglo,  d_agglo);
    cudaGetSymbolAddress((void**)&p_whi,    d_Whi);
    cudaGetSymbolAddress((void**)&p_wlo,    d_Wlo);
    cudaGetSymbolAddress((void**)&p_wihphi, d_Wihphi);
    cudaGetSymbolAddress((void**)&p_wihplo, d_Wihplo);
    cudaGetSymbolAddress((void**)&p_whhp,   d_Whhp);
    cudaGetSymbolAddress((void**)&p_wcth,   d_Wcth);

    cudaFuncSetAttribute(gemm_h<true>,  cudaFuncAttributeMaxDynamicSharedMemorySize, 2 * 4 * ARRB);
    cudaFuncSetAttribute(gemm_h<false>, cudaFuncAttributeMaxDynamicSharedMemorySize, 2 * 3 * ARRB);
    cudaFuncSetAttribute(gemm_gru, cudaFuncAttributeMaxDynamicSharedMemorySize, FUSE_SMEM);

    // CSR build
    k_zero<<<(NODES + 255) / 256, 256>>>();
    k_count<<<EDGES / 256, 256>>>(ei, mask);
    k_scan<<<1, 1024>>>();
    k_fill<<<EDGES / 256, 256>>>(ei, mask, ew);

    // splits + permutes
    k_split_x<<<(NODES * Dd / 2 + 255) / 256, 256>>>(x);
    k_split_W<<<(Dd * Dd / 2 + 255) / 256, 256>>>(W);
    k_permsplit<<<(G3D * Dd / 2 + 255) / 256, 256>>>(Wih, Whh, bih, bhh);

    // Wct = Wih(perm) @ W^T : accurate 3-product
    {
        dim3 grid(Dd / 128, G3D / 128);     // (2, 6)
        gemm_h<true><<<grid, 256, 2 * 4 * ARRB>>>(p_wihphi, p_wihplo, p_whi, p_wlo,
                                                  p_wct, nullptr, Dd, Dd);
    }
    k_round_wct<<<(G3D * Dd / 2 + 255) / 256, 256>>>();

    // aggx = segment_sum(x[u] * w, v), split fp16
    k_aggregate<<<NODES, 64>>>(x);

    // gi = aggx @ Wct^T + bihp   (permuted-col layout; 2-product)
    {
        dim3 grid(G3D / 128, NODES / 128);  // (6, 256)
        gemm_h<false><<<grid, 256, 2 * 3 * ARRB>>>(p_agghi, p_agglo, p_wcth, nullptr,
                                                   p_gi, p_bihp, G3D, Dd);
    }

    // gh = x @ Whh(perm)^T fused with GRU -> out
    {
        dim3 grid(G3D / 96, NODES / 128);   // (8, 256)
        gemm_gru<<<grid, 256, FUSE_SMEM>>>(p_xhi, p_xlo, p_whhp,
                                           p_gi, p_bhhp, x, mask, out, Dd);
    }
}

// round 8
// speedup vs baseline: 1.5013x; 1.1606x over previous
#include <cuda_runtime.h>
#include <cuda_fp16.h>
#include <math.h>
#include <cstdint>

#define Bb 8
#define Nn 4096
#define Dd 256
#define Ee 65536
#define NODES (Bb * Nn)        // 32768
#define EDGES (Bb * Ee)        // 524288
#define G3D   (3 * Dd)         // 768

// ---------------- scratch (static device globals; no allocation) -------------
__device__ float d_gi[NODES * G3D];                // permuted-col layout
__device__ float d_Wct[G3D * Dd];                  // (Wih @ W^T), permuted rows (fp32)
__device__ __half d_xh[NODES * Dd];                // x rounded fp16
__device__ __half d_aggh[NODES * Dd];              // agg rounded fp16
__device__ __half d_Whi[Dd * Dd];                  // W split (for accurate Wct)
__device__ __half d_Wlo[Dd * Dd];
__device__ __half d_Wihphi[G3D * Dd];              // Wih, rows permuted, split
__device__ __half d_Wihplo[G3D * Dd];
__device__ __half d_Whhp[G3D * Dd];                // Whh, rows permuted, fp16
__device__ __half d_Wcth[G3D * Dd];                // Wct rounded fp16
__device__ float d_bihp[G3D];
__device__ float d_bhhp[G3D];
__device__ int   d_counts[NODES];
__device__ int   d_cursor[NODES];
__device__ int   d_rowptr[NODES + 1];
__device__ int   d_esrc[EDGES];
__device__ float d_eww[EDGES];

// permutation: orig row o = g*256+d  ->  o' = (d>>5)*96 + g*32 + (d&31)

// ---------------- CSR construction -------------------------------------------
__global__ void k_zero() {
    int i = blockIdx.x * blockDim.x + threadIdx.x;
    if (i < NODES) { d_counts[i] = 0; d_cursor[i] = 0; }
}

__global__ void k_count(const int* __restrict__ ei, const int* __restrict__ mask) {
    int idx = blockIdx.x * blockDim.x + threadIdx.x;
    if (idx >= EDGES) return;
    int b = idx >> 16;
    int e = idx & (Ee - 1);
    int u = ei[((b << 1) + 0) * Ee + e];
    int v = ei[((b << 1) + 1) * Ee + e];
    if (mask[(b << 12) + u] > 0 && mask[(b << 12) + v] > 0)
        atomicAdd(&d_counts[(b << 12) + v], 1);
}

__global__ void k_scan() {
    __shared__ int sums[1024];
    int t = threadIdx.x;
    int base = t * 32;
    int s = 0;
    #pragma unroll
    for (int i = 0; i < 32; i++) s += d_counts[base + i];
    sums[t] = s;
    __syncthreads();
    for (int off = 1; off < 1024; off <<= 1) {
        int v = (t >= off) ? sums[t - off] : 0;
        __syncthreads();
        sums[t] += v;
        __syncthreads();
    }
    int run = (t == 0) ? 0 : sums[t - 1];
    #pragma unroll
    for (int i = 0; i < 32; i++) {
        d_rowptr[base + i] = run;
        run += d_counts[base + i];
    }
    if (t == 1023) d_rowptr[NODES] = sums[1023];
}

__global__ void k_fill(const int* __restrict__ ei, const int* __restrict__ mask,
                       const float* __restrict__ ew) {
    int idx = blockIdx.x * blockDim.x + threadIdx.x;
    if (idx >= EDGES) return;
    int b = idx >> 16;
    int e = idx & (Ee - 1);
    int u = ei[((b << 1) + 0) * Ee + e];
    int v = ei[((b << 1) + 1) * Ee + e];
    if (mask[(b << 12) + u] > 0 && mask[(b << 12) + v] > 0) {
        int node = (b << 12) + v;
        int pos = d_rowptr[node] + atomicAdd(&d_cursor[node], 1);
        d_esrc[pos] = u;
        d_eww[pos]  = ew[idx];
    }
}

// ---------------- split / round helpers ---------------------------------------
__device__ __forceinline__ void split2h(float a, float b, __half2& hi, __half2& lo) {
    hi = __floats2half2_rn(a, b);
    lo = __floats2half2_rn(a - __low2float(hi), b - __high2float(hi));
}

__global__ void k_round_x(const float* __restrict__ x) {
    int idx = blockIdx.x * blockDim.x + threadIdx.x;
    if (idx >= NODES * Dd / 2) return;
    float2 v = ((const float2*)x)[idx];
    ((__half2*)d_xh)[idx] = __floats2half2_rn(v.x, v.y);
}

__global__ void k_split_W(const float* __restrict__ W) {
    int idx = blockIdx.x * blockDim.x + threadIdx.x;
    if (idx >= Dd * Dd / 2) return;
    float2 v = ((const float2*)W)[idx];
    __half2 h, l;
    split2h(v.x, v.y, h, l);
    ((__half2*)d_Whi)[idx] = h;
    ((__half2*)d_Wlo)[idx] = l;
}

// permuted-row: Wih split (A of Wct GEMM), Whh fp16 (B of gh GEMM), biases
__global__ void k_permsplit(const float* __restrict__ wih, const float* __restrict__ whh,
                            const float* __restrict__ bih, const float* __restrict__ bhh) {
    int idx = blockIdx.x * blockDim.x + threadIdx.x;   // G3D * Dd/2
    if (idx >= G3D * Dd / 2) return;
    int o    = idx / (Dd / 2);
    int col2 = idx - o * (Dd / 2);
    int g = o >> 8, d = o & 255;
    int op = (d >> 5) * 96 + g * 32 + (d & 31);
    size_t dst = (size_t)op * (Dd / 2) + col2;
    float2 a = ((const float2*)wih)[idx];
    __half2 h, l;
    split2h(a.x, a.y, h, l);
    ((__half2*)d_Wihphi)[dst] = h;
    ((__half2*)d_Wihplo)[dst] = l;
    float2 b = ((const float2*)whh)[idx];
    ((__half2*)d_Whhp)[dst] = __floats2half2_rn(b.x, b.y);
    if (col2 == 0) {
        d_bihp[op] = bih[o];
        d_bhhp[op] = bhh[o];
    }
}

__global__ void k_round_wct() {
    int idx = blockIdx.x * blockDim.x + threadIdx.x;
    if (idx >= G3D * Dd / 2) return;
    float2 v = ((const float2*)d_Wct)[idx];
    ((__half2*)d_Wcth)[idx] = __floats2half2_rn(v.x, v.y);
}

// ---------------- mma.sync helpers --------------------------------------------
__device__ __forceinline__ uint32_t cvta_s(const void* p) {
    return (uint32_t)__cvta_generic_to_shared(p);
}
__device__ __forceinline__ void ldsm_x4(uint32_t& r0, uint32_t& r1, uint32_t& r2, uint32_t& r3,
                                        uint32_t addr) {
    asm volatile("ldmatrix.sync.aligned.m8n8.x4.shared.b16 {%0,%1,%2,%3}, [%4];"
                 : "=r"(r0), "=r"(r1), "=r"(r2), "=r"(r3) : "r"(addr));
}
__device__ __forceinline__ void ldsm_x2(uint32_t& r0, uint32_t& r1, uint32_t addr) {
    asm volatile("ldmatrix.sync.aligned.m8n8.x2.shared.b16 {%0,%1}, [%2];"
                 : "=r"(r0), "=r"(r1) : "r"(addr));
}
__device__ __forceinline__ void mma_f16(float* d, const uint32_t* a, const uint32_t* b) {
    asm volatile(
        "mma.sync.aligned.m16n8k16.row.col.f32.f16.f16.f32 "
        "{%0,%1,%2,%3}, {%4,%5,%6,%7}, {%8,%9}, {%0,%1,%2,%3};"
        : "+f"(d[0]), "+f"(d[1]), "+f"(d[2]), "+f"(d[3])
        : "r"(a[0]), "r"(a[1]), "r"(a[2]), "r"(a[3]), "r"(b[0]), "r"(b[1]));
}
#define CP16(dst, src) \
    asm volatile("cp.async.cg.shared.global [%0], [%1], 16;" :: "r"(dst), "l"(src))
#define CP_COMMIT() asm volatile("cp.async.commit_group;" ::: "memory")

#define SPAD 40
#define ARRB (128 * SPAD * 2)   // 10240 bytes per 128xBK half array

// ---------------- accurate split GEMM (Wct precompute only) ------------------
#define W_STAGE (4 * ARRB)
#define WCT_SMEM (2 * W_STAGE)

__global__ __launch_bounds__(256, 2) void gemm_wct(
    const __half* __restrict__ Ahi, const __half* __restrict__ Alo,
    const __half* __restrict__ Bhi, const __half* __restrict__ Blo,
    float* __restrict__ C, int N, int K)
{
    extern __shared__ char smem[];
    const uint32_t sb = cvta_s(smem);
    const int t    = threadIdx.x;
    const int wid  = t >> 5;
    const int lane = t & 31;
    const int wm   = wid >> 2;
    const int wn   = wid & 3;
    const int m0   = blockIdx.y * 128;
    const int n0   = blockIdx.x * 128;
    const int lrow = t >> 2;
    const int lc4  = t & 3;

    float acc[4][4][4];
    #pragma unroll
    for (int mf = 0; mf < 4; mf++)
        #pragma unroll
        for (int nf = 0; nf < 4; nf++)
            #pragma unroll
            for (int j = 0; j < 4; j++) acc[mf][nf][j] = 0.0f;

    const int nchunks = K >> 5;

    auto load_stage = [&](int kc, int s) {
        uint32_t base = sb + s * W_STAGE;
        #pragma unroll
        for (int i = 0; i < 2; i++) {
            int row = lrow + i * 64;
            uint32_t doff = (uint32_t)(row * (SPAD * 2) + lc4 * 16);
            size_t asrc = (size_t)(m0 + row) * K + kc * 32 + lc4 * 8;
            size_t bsrc = (size_t)(n0 + row) * K + kc * 32 + lc4 * 8;
            CP16(base + 0 * ARRB + doff, Ahi + asrc);
            CP16(base + 1 * ARRB + doff, Alo + asrc);
            CP16(base + 2 * ARRB + doff, Bhi + bsrc);
            CP16(base + 3 * ARRB + doff, Blo + bsrc);
        }
        CP_COMMIT();
    };

    load_stage(0, 0);

    for (int kc = 0; kc < nchunks; kc++) {
        const int s = kc & 1;
        if (kc + 1 < nchunks) {
            load_stage(kc + 1, s ^ 1);
            asm volatile("cp.async.wait_group 1;" ::: "memory");
        } else {
            asm volatile("cp.async.wait_group 0;" ::: "memory");
        }
        __syncthreads();

        const uint32_t base = sb + s * W_STAGE;
        #pragma unroll
        for (int ks = 0; ks < 2; ks++) {
            const int k0 = ks * 16;
            uint32_t ahi[4][4], alo[4][4], bhi[4][2], blo[4][2];
            #pragma unroll
            for (int mf = 0; mf < 4; mf++) {
                int arow = wm * 64 + mf * 16 + (lane & 15);
                int acol = k0 + ((lane >> 4) & 1) * 8;
                uint32_t ao = (uint32_t)((arow * SPAD + acol) * 2);
                ldsm_x4(ahi[mf][0], ahi[mf][1], ahi[mf][2], ahi[mf][3], base + 0 * ARRB + ao);
                ldsm_x4(alo[mf][0], alo[mf][1], alo[mf][2], alo[mf][3], base + 1 * ARRB + ao);
            }
            #pragma unroll
            for (int nf = 0; nf < 4; nf++) {
                int brow = wn * 32 + nf * 8 + (lane & 7);
                int bcol = k0 + ((lane >> 3) & 1) * 8;
                uint32_t bo = (uint32_t)((brow * SPAD + bcol) * 2);
                ldsm_x2(bhi[nf][0], bhi[nf][1], base + 2 * ARRB + bo);
                ldsm_x2(blo[nf][0], blo[nf][1], base + 3 * ARRB + bo);
            }
            #pragma unroll
            for (int mf = 0; mf < 4; mf++)
                #pragma unroll
                for (int nf = 0; nf < 4; nf++) {
                    mma_f16(acc[mf][nf], ahi[mf], bhi[nf]);
                    mma_f16(acc[mf][nf], alo[mf], bhi[nf]);
                    mma_f16(acc[mf][nf], ahi[mf], blo[nf]);
                }
        }
        __syncthreads();
    }

    const int erow = (lane >> 2);
    const int ecol = (lane & 3) * 2;
    #pragma unroll
    for (int mf = 0; mf < 4; mf++) {
        #pragma unroll
        for (int nf = 0; nf < 4; nf++) {
            int r0 = m0 + wm * 64 + mf * 16 + erow;
            int c0 = n0 + wn * 32 + nf * 8 + ecol;
            *(float2*)(C + (size_t)r0 * N + c0)       = make_float2(acc[mf][nf][0], acc[mf][nf][1]);
            *(float2*)(C + (size_t)(r0 + 8) * N + c0) = make_float2(acc[mf][nf][2], acc[mf][nf][3]);
        }
    }
}

// ---------------- single-product fp16 GEMM (128x128x32): gi ------------------
#define S_STAGE (2 * ARRB)          // Ah + Bh
#define GI_SMEM (2 * S_STAGE)       // 40960

__global__ __launch_bounds__(256, 2) void gemm_1p(
    const __half* __restrict__ Ah, const __half* __restrict__ Bh,
    float* __restrict__ C, const float* __restrict__ bias,
    int N, int K)
{
    extern __shared__ char smem[];
    const uint32_t sb = cvta_s(smem);
    const int t    = threadIdx.x;
    const int wid  = t >> 5;
    const int lane = t & 31;
    const int wm   = wid >> 2;
    const int wn   = wid & 3;
    const int m0   = blockIdx.y * 128;
    const int n0   = blockIdx.x * 128;
    const int lrow = t >> 2;
    const int lc4  = t & 3;

    float acc[4][4][4];
    #pragma unroll
    for (int mf = 0; mf < 4; mf++)
        #pragma unroll
        for (int nf = 0; nf < 4; nf++)
            #pragma unroll
            for (int j = 0; j < 4; j++) acc[mf][nf][j] = 0.0f;

    const int nchunks = K >> 5;

    auto load_stage = [&](int kc, int s) {
        uint32_t base = sb + s * S_STAGE;
        #pragma unroll
        for (int i = 0; i < 2; i++) {
            int row = lrow + i * 64;
            uint32_t doff = (uint32_t)(row * (SPAD * 2) + lc4 * 16);
            size_t asrc = (size_t)(m0 + row) * K + kc * 32 + lc4 * 8;
            size_t bsrc = (size_t)(n0 + row) * K + kc * 32 + lc4 * 8;
            CP16(base + 0 * ARRB + doff, Ah + asrc);
            CP16(base + 1 * ARRB + doff, Bh + bsrc);
        }
        CP_COMMIT();
    };

    load_stage(0, 0);

    for (int kc = 0; kc < nchunks; kc++) {
        const int s = kc & 1;
        if (kc + 1 < nchunks) {
            load_stage(kc + 1, s ^ 1);
            asm volatile("cp.async.wait_group 1;" ::: "memory");
        } else {
            asm volatile("cp.async.wait_group 0;" ::: "memory");
        }
        __syncthreads();

        const uint32_t base = sb + s * S_STAGE;
        #pragma unroll
        for (int ks = 0; ks < 2; ks++) {
            const int k0 = ks * 16;
            uint32_t a[4][4], b[4][2];
            #pragma unroll
            for (int mf = 0; mf < 4; mf++) {
                int arow = wm * 64 + mf * 16 + (lane & 15);
                int acol = k0 + ((lane >> 4) & 1) * 8;
                uint32_t ao = (uint32_t)((arow * SPAD + acol) * 2);
                ldsm_x4(a[mf][0], a[mf][1], a[mf][2], a[mf][3], base + 0 * ARRB + ao);
            }
            #pragma unroll
            for (int nf = 0; nf < 4; nf++) {
                int brow = wn * 32 + nf * 8 + (lane & 7);
                int bcol = k0 + ((lane >> 3) & 1) * 8;
                uint32_t bo = (uint32_t)((brow * SPAD + bcol) * 2);
                ldsm_x2(b[nf][0], b[nf][1], base + 1 * ARRB + bo);
            }
            #pragma unroll
            for (int mf = 0; mf < 4; mf++)
                #pragma unroll
                for (int nf = 0; nf < 4; nf++)
                    mma_f16(acc[mf][nf], a[mf], b[nf]);
        }
        __syncthreads();
    }

    const int erow = (lane >> 2);
    const int ecol = (lane & 3) * 2;
    #pragma unroll
    for (int mf = 0; mf < 4; mf++) {
        #pragma unroll
        for (int nf = 0; nf < 4; nf++) {
            int r0 = m0 + wm * 64 + mf * 16 + erow;
            int c0 = n0 + wn * 32 + nf * 8 + ecol;
            float b0 = bias[c0], b1 = bias[c0 + 1];
            *(float2*)(C + (size_t)r0 * N + c0)       = make_float2(acc[mf][nf][0] + b0, acc[mf][nf][1] + b1);
            *(float2*)(C + (size_t)(r0 + 8) * N + c0) = make_float2(acc[mf][nf][2] + b0, acc[mf][nf][3] + b1);
        }
    }
}

// ---------------- fused gh GEMM (128x96x32, single product) + GRU ------------
#define FB_BYTES (96 * SPAD * 2)                  // 7680
#define F_STAGE (ARRB + FB_BYTES)                 // 17920
#define FUSE_SMEM 51200                           // max(2*F_STAGE=35840, 128*100*4)

__device__ __forceinline__ float sigmoidf_(float x) {
    return 1.0f / (1.0f + __expf(-x));
}

__global__ __launch_bounds__(256, 2) void gemm_gru(
    const __half* __restrict__ Ah, const __half* __restrict__ Bh,
    const float* __restrict__ gi, const float* __restrict__ bhhp,
    const float* __restrict__ x, const int* __restrict__ mask,
    float* __restrict__ out, int K)
{
    extern __shared__ char smem[];
    const uint32_t sb = cvta_s(smem);
    const int t    = threadIdx.x;
    const int wid  = t >> 5;
    const int lane = t & 31;
    const int wm   = wid >> 2;        // 0..1
    const int wn   = wid & 3;         // 0..3 (24-col slices)
    const int m0   = blockIdx.y * 128;
    const int n0   = blockIdx.x * 96;
    const int lrow = t >> 2;
    const int lc4  = t & 3;

    float acc[4][3][4];
    #pragma unroll
    for (int mf = 0; mf < 4; mf++)
        #pragma unroll
        for (int nf = 0; nf < 3; nf++)
            #pragma unroll
            for (int j = 0; j < 4; j++) acc[mf][nf][j] = 0.0f;

    const int nchunks = K >> 5;

    auto load_stage = [&](int kc, int s) {
        uint32_t base = sb + s * F_STAGE;
        #pragma unroll
        for (int i = 0; i < 2; i++) {
            int row = lrow + i * 64;
            uint32_t doff = (uint32_t)(row * (SPAD * 2) + lc4 * 16);
            size_t asrc = (size_t)(m0 + row) * K + kc * 32 + lc4 * 8;
            CP16(base + doff, Ah + asrc);
        }
        {   // B: 96 rows x 4 chunks = 384
            int c = t;
            int row = c >> 2, c4 = c & 3;
            uint32_t doff = (uint32_t)(row * (SPAD * 2) + c4 * 16);
            size_t bsrc = (size_t)(n0 + row) * K + kc * 32 + c4 * 8;
            CP16(base + ARRB + doff, Bh + bsrc);
            if (t < 128) {
                c = t + 256;
                row = c >> 2; c4 = c & 3;
                doff = (uint32_t)(row * (SPAD * 2) + c4 * 16);
                bsrc = (size_t)(n0 + row) * K + kc * 32 + c4 * 8;
                CP16(base + ARRB + doff, Bh + bsrc);
            }
        }
        CP_COMMIT();
    };

    load_stage(0, 0);

    for (int kc = 0; kc < nchunks; kc++) {
        const int s = kc & 1;
        if (kc + 1 < nchunks) {
            load_stage(kc + 1, s ^ 1);
            asm volatile("cp.async.wait_group 1;" ::: "memory");
        } else {
            asm volatile("cp.async.wait_group 0;" ::: "memory");
        }
        __syncthreads();

        const uint32_t base = sb + s * F_STAGE;
        #pragma unroll
        for (int ks = 0; ks < 2; ks++) {
            const int k0 = ks * 16;
            uint32_t a[4][4], b[3][2];
            #pragma unroll
            for (int mf = 0; mf < 4; mf++) {
                int arow = wm * 64 + mf * 16 + (lane & 15);
                int acol = k0 + ((lane >> 4) & 1) * 8;
                uint32_t ao = (uint32_t)((arow * SPAD + acol) * 2);
                ldsm_x4(a[mf][0], a[mf][1], a[mf][2], a[mf][3], base + ao);
            }
            #pragma unroll
            for (int nf = 0; nf < 3; nf++) {
                int brow = wn * 24 + nf * 8 + (lane & 7);
                int bcol = k0 + ((lane >> 3) & 1) * 8;
                uint32_t bo = (uint32_t)((brow * SPAD + bcol) * 2);
                ldsm_x2(b[nf][0], b[nf][1], base + ARRB + bo);
            }
            #pragma unroll
            for (int mf = 0; mf < 4; mf++)
                #pragma unroll
                for (int nf = 0; nf < 3; nf++)
                    mma_f16(acc[mf][nf], a[mf], b[nf]);
        }
        __syncthreads();
    }

    // phase 1: fragments -> smem tile ghs[128][100]
    float* ghs = (float*)smem;
    const int erow = (lane >> 2);
    const int ecol = (lane & 3) * 2;
    #pragma unroll
    for (int mf = 0; mf < 4; mf++) {
        #pragma unroll
        for (int nf = 0; nf < 3; nf++) {
            int r0 = wm * 64 + mf * 16 + erow;
            int c0 = wn * 24 + nf * 8 + ecol;
            *(float2*)&ghs[r0 * 100 + c0]       = make_float2(acc[mf][nf][0], acc[mf][nf][1]);
            *(float2*)&ghs[(r0 + 8) * 100 + c0] = make_float2(acc[mf][nf][2], acc[mf][nf][3]);
        }
    }
    __syncthreads();

    // phase 2: GRU. thread t: feature f = t&31; rows r = (t>>5)*16 + 0..15
    const int f    = t & 31;
    const int rg0  = (t >> 5) * 16;
    const int fglob = blockIdx.x * 32 + f;
    const float bh_r = bhhp[n0 + f];
    const float bh_z = bhhp[n0 + 32 + f];
    const float bh_n = bhhp[n0 + 64 + f];

    #pragma unroll
    for (int i = 0; i < 16; i++) {
        int r = rg0 + i;
        int row_g = m0 + r;
        float valid = (mask[row_g] > 0) ? 1.0f : 0.0f;
        const float* gip = gi + (size_t)row_g * G3D + n0;
        float gi_r = gip[f];
        float gi_z = gip[32 + f];
        float gi_n = gip[64 + f];
        float gh_r = ghs[r * 100 + f]      + bh_r;
        float gh_z = ghs[r * 100 + 32 + f] + bh_z;
        float gh_n = ghs[r * 100 + 64 + f] + bh_n;
        float xv = x[(size_t)row_g * Dd + fglob];
        float rr = sigmoidf_(gi_r + gh_r);
        float zz = sigmoidf_(gi_z + gh_z);
        float nn = tanhf(gi_n + rr * gh_n);
        out[(size_t)row_g * Dd + fglob] = ((1.0f - zz) * nn + zz * xv) * valid;
    }
}

// ---------------- aggregation: gathers fp16 x, writes fp16 agg ---------------
__global__ void k_aggregate() {
    int node = blockIdx.x;
    int t = threadIdx.x;               // 0..63, owns 4 halves of the 256-row
    int start = d_rowptr[node];
    int end   = d_rowptr[node + 1];
    int bBase = (node >> 12) << 12;
    float4 acc = make_float4(0.f, 0.f, 0.f, 0.f);
    for (int j = start; j < end; j++) {
        int src = d_esrc[j];
        float w = d_eww[j];
        uint2 p = __ldg((const uint2*)&d_xh[(size_t)(bBase + src) * Dd] + t);
        __half2 h0 = *(__half2*)&p.x;
        __half2 h1 = *(__half2*)&p.y;
        float2 f0 = __half22float2(h0);
        float2 f1 = __half22float2(h1);
        acc.x += w * f0.x; acc.y += w * f0.y; acc.z += w * f1.x; acc.w += w * f1.y;
    }
    uint2 o;
    __half2 r0 = __floats2half2_rn(acc.x, acc.y);
    __half2 r1 = __floats2half2_rn(acc.z, acc.w);
    o.x = *(uint32_t*)&r0;
    o.y = *(uint32_t*)&r1;
    ((uint2*)&d_aggh[(size_t)node * Dd])[t] = o;
}

// ---------------- launch ------------------------------------------------------
extern "C" void kernel_launch(void* const* d_in, const int* in_sizes, int n_in,
                              void* d_out, int out_size) {
    const float* x    = (const float*)d_in[0];
    const int*   ei   = (const int*)  d_in[1];
    const float* ew   = (const float*)d_in[2];
    const int*   mask = (const int*)  d_in[3];
    const float* W    = (const float*)d_in[4];
    const float* Wih  = (const float*)d_in[5];
    const float* Whh  = (const float*)d_in[6];
    const float* bih  = (const float*)d_in[7];
    const float* bhh  = (const float*)d_in[8];
    float* out = (float*)d_out;

    float *p_gi, *p_wct, *p_bihp, *p_bhhp;
    __half *p_xh, *p_aggh, *p_whi, *p_wlo, *p_wihphi, *p_wihplo, *p_whhp, *p_wcth;
    cudaGetSymbolAddress((void**)&p_gi,     d_gi);
    cudaGetSymbolAddress((void**)&p_wct,    d_Wct);
    cudaGetSymbolAddress((void**)&p_bihp,   d_bihp);
    cudaGetSymbolAddress((void**)&p_bhhp,   d_bhhp);
    cudaGetSymbolAddress((void**)&p_xh,     d_xh);
    cudaGetSymbolAddress((void**)&p_aggh,   d_aggh);
    cudaGetSymbolAddress((void**)&p_whi,    d_Whi);
    cudaGetSymbolAddress((void**)&p_wlo,    d_Wlo);
    cudaGetSymbolAddress((void**)&p_wihphi, d_Wihphi);
    cudaGetSymbolAddress((void**)&p_wihplo, d_Wihplo);
    cudaGetSymbolAddress((void**)&p_whhp,   d_Whhp);
    cudaGetSymbolAddress((void**)&p_wcth,   d_Wcth);

    cudaFuncSetAttribute(gemm_wct, cudaFuncAttributeMaxDynamicSharedMemorySize, WCT_SMEM);
    cudaFuncSetAttribute(gemm_1p,  cudaFuncAttributeMaxDynamicSharedMemorySize, GI_SMEM);
    cudaFuncSetAttribute(gemm_gru, cudaFuncAttributeMaxDynamicSharedMemorySize, FUSE_SMEM);

    // CSR build
    k_zero<<<(NODES + 255) / 256, 256>>>();
    k_count<<<EDGES / 256, 256>>>(ei, mask);
    k_scan<<<1, 1024>>>();
    k_fill<<<EDGES / 256, 256>>>(ei, mask, ew);

    // rounds / splits / permutes
    k_round_x<<<(NODES * Dd / 2 + 255) / 256, 256>>>(x);
    k_split_W<<<(Dd * Dd / 2 + 255) / 256, 256>>>(W);
    k_permsplit<<<(G3D * Dd / 2 + 255) / 256, 256>>>(Wih, Whh, bih, bhh);

    // Wct = Wih(perm) @ W^T : accurate 3-product
    {
        dim3 grid(Dd / 128, G3D / 128);     // (2, 6)
        gemm_wct<<<grid, 256, WCT_SMEM>>>(p_wihphi, p_wihplo, p_whi, p_wlo, p_wct, Dd, Dd);
    }
    k_round_wct<<<(G3D * Dd / 2 + 255) / 256, 256>>>();

    // aggx (fp16 gather, fp32 accumulate, fp16 store)
    k_aggregate<<<NODES, 64>>>();

    // gi = aggx @ Wct^T + bihp   (permuted-col layout; single product)
    {
        dim3 grid(G3D / 128, NODES / 128);  // (6, 256)
        gemm_1p<<<grid, 256, GI_SMEM>>>(p_aggh, p_wcth, p_gi, p_bihp, G3D, Dd);
    }

    // gh = x @ Whh(perm)^T fused with GRU -> out
    {
        dim3 grid(G3D / 96, NODES / 128);   // (8, 256)
        gemm_gru<<<grid, 256, FUSE_SMEM>>>(p_xh, p_whhp, p_gi, p_bhhp, x, mask, out, Dd);
    }
}

// round 10
// speedup vs baseline: 1.8888x; 1.2582x over previous
#include <cuda_runtime.h>
#include <cuda_fp16.h>
#include <math.h>
#include <cstdint>

#define Bb 8
#define Nn 4096
#define Dd 256
#define Ee 65536
#define NODES (Bb * Nn)        // 32768
#define EDGES (Bb * Ee)        // 524288
#define G3D   (3 * Dd)         // 768

// ---------------- scratch (static device globals; no allocation) -------------
__device__ float d_Wct[G3D * Dd];                  // (Wih @ W^T), permuted rows (fp32)
__device__ __half d_xh[NODES * Dd];                // x rounded fp16
__device__ __half d_aggh[NODES * Dd];              // agg rounded fp16
__device__ __half d_Whi[Dd * Dd];                  // W split (for accurate Wct)
__device__ __half d_Wlo[Dd * Dd];
__device__ __half d_Wihphi[G3D * Dd];              // Wih, rows permuted, split
__device__ __half d_Wihplo[G3D * Dd];
__device__ __half d_Whhp[G3D * Dd];                // Whh, rows permuted, fp16
__device__ __half d_Wcth[G3D * Dd];                // Wct rounded fp16
__device__ float d_bihp[G3D];
__device__ float d_bhhp[G3D];
__device__ int   d_counts[NODES];
__device__ int   d_cursor[NODES];
__device__ int   d_rowptr[NODES + 1];
__device__ int   d_esrc[EDGES];
__device__ float d_eww[EDGES];

// permutation: gate g of feature d -> op = (d>>5)*96 + ((d&31)>>3)*24 + g*8 + (d&7)
// so that in a 128x96 tile (warp = 24 cols), nf blocks 0/1/2 are gates r/z/n
// of the SAME feature at the SAME fragment position.

// ---------------- CSR construction -------------------------------------------
__global__ void k_zero() {
    int i = blockIdx.x * blockDim.x + threadIdx.x;
    if (i < NODES) { d_counts[i] = 0; d_cursor[i] = 0; }
}

__global__ void k_count(const int* __restrict__ ei, const int* __restrict__ mask) {
    int idx = blockIdx.x * blockDim.x + threadIdx.x;
    if (idx >= EDGES) return;
    int b = idx >> 16;
    int e = idx & (Ee - 1);
    int u = ei[((b << 1) + 0) * Ee + e];
    int v = ei[((b << 1) + 1) * Ee + e];
    if (mask[(b << 12) + u] > 0 && mask[(b << 12) + v] > 0)
        atomicAdd(&d_counts[(b << 12) + v], 1);
}

__global__ void k_scan() {
    __shared__ int sums[1024];
    int t = threadIdx.x;
    int base = t * 32;
    int s = 0;
    #pragma unroll
    for (int i = 0; i < 32; i++) s += d_counts[base + i];
    sums[t] = s;
    __syncthreads();
    for (int off = 1; off < 1024; off <<= 1) {
        int v = (t >= off) ? sums[t - off] : 0;
        __syncthreads();
        sums[t] += v;
        __syncthreads();
    }
    int run = (t == 0) ? 0 : sums[t - 1];
    #pragma unroll
    for (int i = 0; i < 32; i++) {
        d_rowptr[base + i] = run;
        run += d_counts[base + i];
    }
    if (t == 1023) d_rowptr[NODES] = sums[1023];
}

__global__ void k_fill(const int* __restrict__ ei, const int* __restrict__ mask,
                       const float* __restrict__ ew) {
    int idx = blockIdx.x * blockDim.x + threadIdx.x;
    if (idx >= EDGES) return;
    int b = idx >> 16;
    int e = idx & (Ee - 1);
    int u = ei[((b << 1) + 0) * Ee + e];
    int v = ei[((b << 1) + 1) * Ee + e];
    if (mask[(b << 12) + u] > 0 && mask[(b << 12) + v] > 0) {
        int node = (b << 12) + v;
        int pos = d_rowptr[node] + atomicAdd(&d_cursor[node], 1);
        d_esrc[pos] = u;
        d_eww[pos]  = ew[idx];
    }
}

// ---------------- split / round helpers ---------------------------------------
__device__ __forceinline__ void split2h(float a, float b, __half2& hi, __half2& lo) {
    hi = __floats2half2_rn(a, b);
    lo = __floats2half2_rn(a - __low2float(hi), b - __high2float(hi));
}

__global__ void k_round_x(const float* __restrict__ x) {
    int idx = blockIdx.x * blockDim.x + threadIdx.x;
    if (idx >= NODES * Dd / 2) return;
    float2 v = ((const float2*)x)[idx];
    ((__half2*)d_xh)[idx] = __floats2half2_rn(v.x, v.y);
}

__global__ void k_split_W(const float* __restrict__ W) {
    int idx = blockIdx.x * blockDim.x + threadIdx.x;
    if (idx >= Dd * Dd / 2) return;
    float2 v = ((const float2*)W)[idx];
    __half2 h, l;
    split2h(v.x, v.y, h, l);
    ((__half2*)d_Whi)[idx] = h;
    ((__half2*)d_Wlo)[idx] = l;
}

// permuted-row: Wih split (A of Wct GEMM), Whh fp16 (B of gh GEMM), biases
__global__ void k_permsplit(const float* __restrict__ wih, const float* __restrict__ whh,
                            const float* __restrict__ bih, const float* __restrict__ bhh) {
    int idx = blockIdx.x * blockDim.x + threadIdx.x;   // G3D * Dd/2
    if (idx >= G3D * Dd / 2) return;
    int o    = idx / (Dd / 2);
    int col2 = idx - o * (Dd / 2);
    int g = o >> 8, d = o & 255;
    int op = (d >> 5) * 96 + ((d & 31) >> 3) * 24 + g * 8 + (d & 7);
    size_t dst = (size_t)op * (Dd / 2) + col2;
    float2 a = ((const float2*)wih)[idx];
    __half2 h, l;
    split2h(a.x, a.y, h, l);
    ((__half2*)d_Wihphi)[dst] = h;
    ((__half2*)d_Wihplo)[dst] = l;
    float2 b = ((const float2*)whh)[idx];
    ((__half2*)d_Whhp)[dst] = __floats2half2_rn(b.x, b.y);
    if (col2 == 0) {
        d_bihp[op] = bih[o];
        d_bhhp[op] = bhh[o];
    }
}

__global__ void k_round_wct() {
    int idx = blockIdx.x * blockDim.x + threadIdx.x;
    if (idx >= G3D * Dd / 2) return;
    float2 v = ((const float2*)d_Wct)[idx];
    ((__half2*)d_Wcth)[idx] = __floats2half2_rn(v.x, v.y);
}

// ---------------- mma.sync helpers --------------------------------------------
__device__ __forceinline__ uint32_t cvta_s(const void* p) {
    return (uint32_t)__cvta_generic_to_shared(p);
}
__device__ __forceinline__ void ldsm_x4(uint32_t& r0, uint32_t& r1, uint32_t& r2, uint32_t& r3,
                                        uint32_t addr) {
    asm volatile("ldmatrix.sync.aligned.m8n8.x4.shared.b16 {%0,%1,%2,%3}, [%4];"
                 : "=r"(r0), "=r"(r1), "=r"(r2), "=r"(r3) : "r"(addr));
}
__device__ __forceinline__ void ldsm_x2(uint32_t& r0, uint32_t& r1, uint32_t addr) {
    asm volatile("ldmatrix.sync.aligned.m8n8.x2.shared.b16 {%0,%1}, [%2];"
                 : "=r"(r0), "=r"(r1) : "r"(addr));
}
__device__ __forceinline__ void mma_f16(float* d, const uint32_t* a, const uint32_t* b) {
    asm volatile(
        "mma.sync.aligned.m16n8k16.row.col.f32.f16.f16.f32 "
        "{%0,%1,%2,%3}, {%4,%5,%6,%7}, {%8,%9}, {%0,%1,%2,%3};"
        : "+f"(d[0]), "+f"(d[1]), "+f"(d[2]), "+f"(d[3])
        : "r"(a[0]), "r"(a[1]), "r"(a[2]), "r"(a[3]), "r"(b[0]), "r"(b[1]));
}
#define CP16(dst, src) \
    asm volatile("cp.async.cg.shared.global [%0], [%1], 16;" :: "r"(dst), "l"(src))
#define CP_COMMIT() asm volatile("cp.async.commit_group;" ::: "memory")

#define SPAD 40
#define ARRB (128 * SPAD * 2)   // 10240 bytes per 128xBK half array

// ---------------- accurate split GEMM (Wct precompute only) ------------------
#define W_STAGE (4 * ARRB)
#define WCT_SMEM (2 * W_STAGE)

__global__ __launch_bounds__(256, 2) void gemm_wct(
    const __half* __restrict__ Ahi, const __half* __restrict__ Alo,
    const __half* __restrict__ Bhi, const __half* __restrict__ Blo,
    float* __restrict__ C, int N, int K)
{
    extern __shared__ char smem[];
    const uint32_t sb = cvta_s(smem);
    const int t    = threadIdx.x;
    const int wid  = t >> 5;
    const int lane = t & 31;
    const int wm   = wid >> 2;
    const int wn   = wid & 3;
    const int m0   = blockIdx.y * 128;
    const int n0   = blockIdx.x * 128;
    const int lrow = t >> 2;
    const int lc4  = t & 3;

    float acc[4][4][4];
    #pragma unroll
    for (int mf = 0; mf < 4; mf++)
        #pragma unroll
        for (int nf = 0; nf < 4; nf++)
            #pragma unroll
            for (int j = 0; j < 4; j++) acc[mf][nf][j] = 0.0f;

    const int nchunks = K >> 5;

    auto load_stage = [&](int kc, int s) {
        uint32_t base = sb + s * W_STAGE;
        #pragma unroll
        for (int i = 0; i < 2; i++) {
            int row = lrow + i * 64;
            uint32_t doff = (uint32_t)(row * (SPAD * 2) + lc4 * 16);
            size_t asrc = (size_t)(m0 + row) * K + kc * 32 + lc4 * 8;
            size_t bsrc = (size_t)(n0 + row) * K + kc * 32 + lc4 * 8;
            CP16(base + 0 * ARRB + doff, Ahi + asrc);
            CP16(base + 1 * ARRB + doff, Alo + asrc);
            CP16(base + 2 * ARRB + doff, Bhi + bsrc);
            CP16(base + 3 * ARRB + doff, Blo + bsrc);
        }
        CP_COMMIT();
    };

    load_stage(0, 0);

    for (int kc = 0; kc < nchunks; kc++) {
        const int s = kc & 1;
        if (kc + 1 < nchunks) {
            load_stage(kc + 1, s ^ 1);
            asm volatile("cp.async.wait_group 1;" ::: "memory");
        } else {
            asm volatile("cp.async.wait_group 0;" ::: "memory");
        }
        __syncthreads();

        const uint32_t base = sb + s * W_STAGE;
        #pragma unroll
        for (int ks = 0; ks < 2; ks++) {
            const int k0 = ks * 16;
            uint32_t ahi[4][4], alo[4][4], bhi[4][2], blo[4][2];
            #pragma unroll
            for (int mf = 0; mf < 4; mf++) {
                int arow = wm * 64 + mf * 16 + (lane & 15);
                int acol = k0 + ((lane >> 4) & 1) * 8;
                uint32_t ao = (uint32_t)((arow * SPAD + acol) * 2);
                ldsm_x4(ahi[mf][0], ahi[mf][1], ahi[mf][2], ahi[mf][3], base + 0 * ARRB + ao);
                ldsm_x4(alo[mf][0], alo[mf][1], alo[mf][2], alo[mf][3], base + 1 * ARRB + ao);
            }
            #pragma unroll
            for (int nf = 0; nf < 4; nf++) {
                int brow = wn * 32 + nf * 8 + (lane & 7);
                int bcol = k0 + ((lane >> 3) & 1) * 8;
                uint32_t bo = (uint32_t)((brow * SPAD + bcol) * 2);
                ldsm_x2(bhi[nf][0], bhi[nf][1], base + 2 * ARRB + bo);
                ldsm_x2(blo[nf][0], blo[nf][1], base + 3 * ARRB + bo);
            }
            #pragma unroll
            for (int mf = 0; mf < 4; mf++)
                #pragma unroll
                for (int nf = 0; nf < 4; nf++) {
                    mma_f16(acc[mf][nf], ahi[mf], bhi[nf]);
                    mma_f16(acc[mf][nf], alo[mf], bhi[nf]);
                    mma_f16(acc[mf][nf], ahi[mf], blo[nf]);
                }
        }
        __syncthreads();
    }

    const int erow = (lane >> 2);
    const int ecol = (lane & 3) * 2;
    #pragma unroll
    for (int mf = 0; mf < 4; mf++) {
        #pragma unroll
        for (int nf = 0; nf < 4; nf++) {
            int r0 = m0 + wm * 64 + mf * 16 + erow;
            int c0 = n0 + wn * 32 + nf * 8 + ecol;
            *(float2*)(C + (size_t)r0 * N + c0)       = make_float2(acc[mf][nf][0], acc[mf][nf][1]);
            *(float2*)(C + (size_t)(r0 + 8) * N + c0) = make_float2(acc[mf][nf][2], acc[mf][nf][3]);
        }
    }
}

// ---------------- fully fused: gi GEMM + gh GEMM + register GRU --------------
// Tile 128x96; A1 = aggh, B1 = Wcth (gi); A2 = xh, B2 = Whhp (gh).
// nf index == gate index thanks to the fine permutation; GRU runs on fragments.
#define FBB (96 * SPAD * 2)                       // 7680
#define F_A1 0
#define F_A2 ARRB
#define F_B1 (2 * ARRB)
#define F_B2 (2 * ARRB + FBB)
#define F_STAGE (2 * ARRB + 2 * FBB)              // 35840
#define FUSE_SMEM (2 * F_STAGE)                   // 71680

__device__ __forceinline__ float sigmoidf_(float x) {
    return 1.0f / (1.0f + __expf(-x));
}

__global__ __launch_bounds__(256, 2) void gemm2_gru(
    const __half* __restrict__ A1, const __half* __restrict__ B1,
    const __half* __restrict__ A2, const __half* __restrict__ B2,
    const float* __restrict__ bihp, const float* __restrict__ bhhp,
    const float* __restrict__ x, const int* __restrict__ mask,
    float* __restrict__ out, int K)
{
    extern __shared__ char smem[];
    const uint32_t sb = cvta_s(smem);
    const int t    = threadIdx.x;
    const int wid  = t >> 5;
    const int lane = t & 31;
    const int wm   = wid >> 2;        // 0..1
    const int wn   = wid & 3;         // 0..3 (24-col slices)
    const int m0   = blockIdx.y * 128;
    const int n0   = blockIdx.x * 96;
    const int lrow = t >> 2;
    const int lc4  = t & 3;

    float acci[4][3][4];
    float acch[4][3][4];
    #pragma unroll
    for (int mf = 0; mf < 4; mf++)
        #pragma unroll
        for (int nf = 0; nf < 3; nf++)
            #pragma unroll
            for (int j = 0; j < 4; j++) { acci[mf][nf][j] = 0.0f; acch[mf][nf][j] = 0.0f; }

    const int nchunks = K >> 5;

    auto load_stage = [&](int kc, int s) {
        uint32_t base = sb + s * F_STAGE;
        #pragma unroll
        for (int i = 0; i < 2; i++) {
            int row = lrow + i * 64;
            uint32_t doff = (uint32_t)(row * (SPAD * 2) + lc4 * 16);
            size_t asrc = (size_t)(m0 + row) * K + kc * 32 + lc4 * 8;
            CP16(base + F_A1 + doff, A1 + asrc);
            CP16(base + F_A2 + doff, A2 + asrc);
        }
        {   // B arrays: 96 rows x 4 chunks = 384 each
            int c = t;
            int row = c >> 2, c4 = c & 3;
            uint32_t doff = (uint32_t)(row * (SPAD * 2) + c4 * 16);
            size_t bsrc = (size_t)(n0 + row) * K + kc * 32 + c4 * 8;
            CP16(base + F_B1 + doff, B1 + bsrc);
            CP16(base + F_B2 + doff, B2 + bsrc);
            if (t < 128) {
                c = t + 256;
                row = c >> 2; c4 = c & 3;
                doff = (uint32_t)(row * (SPAD * 2) + c4 * 16);
                bsrc = (size_t)(n0 + row) * K + kc * 32 + c4 * 8;
                CP16(base + F_B1 + doff, B1 + bsrc);
                CP16(base + F_B2 + doff, B2 + bsrc);
            }
        }
        CP_COMMIT();
    };

    load_stage(0, 0);

    for (int kc = 0; kc < nchunks; kc++) {
        const int s = kc & 1;
        if (kc + 1 < nchunks) {
            load_stage(kc + 1, s ^ 1);
            asm volatile("cp.async.wait_group 1;" ::: "memory");
        } else {
            asm volatile("cp.async.wait_group 0;" ::: "memory");
        }
        __syncthreads();

        const uint32_t base = sb + s * F_STAGE;
        #pragma unroll
        for (int ks = 0; ks < 2; ks++) {
            const int k0 = ks * 16;
            const int arowb = wm * 64 + (lane & 15);
            const int acol  = k0 + ((lane >> 4) & 1) * 8;
            const int browb = wn * 24 + (lane & 7);
            const int bcol  = k0 + ((lane >> 3) & 1) * 8;

            {   // gi: A1 x B1
                uint32_t a[4][4], b[3][2];
                #pragma unroll
                for (int mf = 0; mf < 4; mf++) {
                    uint32_t ao = (uint32_t)(((arowb + mf * 16) * SPAD + acol) * 2);
                    ldsm_x4(a[mf][0], a[mf][1], a[mf][2], a[mf][3], base + F_A1 + ao);
                }
                #pragma unroll
                for (int nf = 0; nf < 3; nf++) {
                    uint32_t bo = (uint32_t)(((browb + nf * 8) * SPAD + bcol) * 2);
                    ldsm_x2(b[nf][0], b[nf][1], base + F_B1 + bo);
                }
                #pragma unroll
                for (int mf = 0; mf < 4; mf++)
                    #pragma unroll
                    for (int nf = 0; nf < 3; nf++)
                        mma_f16(acci[mf][nf], a[mf], b[nf]);
            }
            {   // gh: A2 x B2
                uint32_t a[4][4], b[3][2];
                #pragma unroll
                for (int mf = 0; mf < 4; mf++) {
                    uint32_t ao = (uint32_t)(((arowb + mf * 16) * SPAD + acol) * 2);
                    ldsm_x4(a[mf][0], a[mf][1], a[mf][2], a[mf][3], base + F_A2 + ao);
                }
                #pragma unroll
                for (int nf = 0; nf < 3; nf++) {
                    uint32_t bo = (uint32_t)(((browb + nf * 8) * SPAD + bcol) * 2);
                    ldsm_x2(b[nf][0], b[nf][1], base + F_B2 + bo);
                }
                #pragma unroll
                for (int mf = 0; mf < 4; mf++)
                    #pragma unroll
                    for (int nf = 0; nf < 3; nf++)
                        mma_f16(acch[mf][nf], a[mf], b[nf]);
            }
        }
        __syncthreads();
    }

    // -------- register GRU epilogue --------
    // thread owns: rows m0 + wm*64 + mf*16 + (lane>>2) (+8), features
    // f = blockIdx.x*32 + wn*8 + (lane&3)*2 (+1); gate g == nf.
    const int erow = lane >> 2;
    const int fl0  = (lane & 3) * 2;                 // feature within warp slice
    const int fg0  = blockIdx.x * 32 + wn * 8 + fl0; // global feature
    const int bb   = n0 + wn * 24 + fl0;             // permuted bias base (g=0)

    float2 bi_r = *(const float2*)&bihp[bb];
    float2 bi_z = *(const float2*)&bihp[bb + 8];
    float2 bi_n = *(const float2*)&bihp[bb + 16];
    float2 bh_r = *(const float2*)&bhhp[bb];
    float2 bh_z = *(const float2*)&bhhp[bb + 8];
    float2 bh_n = *(const float2*)&bhhp[bb + 16];

    #pragma unroll
    for (int mf = 0; mf < 4; mf++) {
        #pragma unroll
        for (int half = 0; half < 2; half++) {       // j pair: {0,1} row0, {2,3} row0+8
            int row = m0 + wm * 64 + mf * 16 + erow + half * 8;
            float valid = (mask[row] > 0) ? 1.0f : 0.0f;
            float2 xv = *(const float2*)&x[(size_t)row * Dd + fg0];
            int j0 = half * 2;
            float o0, o1;
            {
                float rr = sigmoidf_(acci[mf][0][j0] + bi_r.x + acch[mf][0][j0] + bh_r.x);
                float zz = sigmoidf_(acci[mf][1][j0] + bi_z.x + acch[mf][1][j0] + bh_z.x);
                float nn = tanhf(acci[mf][2][j0] + bi_n.x + rr * (acch[mf][2][j0] + bh_n.x));
                o0 = ((1.0f - zz) * nn + zz * xv.x) * valid;
            }
            {
                float rr = sigmoidf_(acci[mf][0][j0+1] + bi_r.y + acch[mf][0][j0+1] + bh_r.y);
                float zz = sigmoidf_(acci[mf][1][j0+1] + bi_z.y + acch[mf][1][j0+1] + bh_z.y);
                float nn = tanhf(acci[mf][2][j0+1] + bi_n.y + rr * (acch[mf][2][j0+1] + bh_n.y));
                o1 = ((1.0f - zz) * nn + zz * xv.y) * valid;
            }
            *(float2*)&out[(size_t)row * Dd + fg0] = make_float2(o0, o1);
        }
    }
}

// ---------------- aggregation: gathers fp16 x, writes fp16 agg ---------------
__global__ void k_aggregate() {
    int node = blockIdx.x;
    int t = threadIdx.x;               // 0..63, owns 4 halves of the 256-row
    int start = d_rowptr[node];
    int end   = d_rowptr[node + 1];
    int bBase = (node >> 12) << 12;
    float4 acc = make_float4(0.f, 0.f, 0.f, 0.f);
    for (int j = start; j < end; j++) {
        int src = d_esrc[j];
        float w = d_eww[j];
        uint2 p = __ldg((const uint2*)&d_xh[(size_t)(bBase + src) * Dd] + t);
        __half2 h0 = *(__half2*)&p.x;
        __half2 h1 = *(__half2*)&p.y;
        float2 f0 = __half22float2(h0);
        float2 f1 = __half22float2(h1);
        acc.x += w * f0.x; acc.y += w * f0.y; acc.z += w * f1.x; acc.w += w * f1.y;
    }
    uint2 o;
    __half2 r0 = __floats2half2_rn(acc.x, acc.y);
    __half2 r1 = __floats2half2_rn(acc.z, acc.w);
    o.x = *(uint32_t*)&r0;
    o.y = *(uint32_t*)&r1;
    ((uint2*)&d_aggh[(size_t)node * Dd])[t] = o;
}

// ---------------- launch ------------------------------------------------------
extern "C" void kernel_launch(void* const* d_in, const int* in_sizes, int n_in,
                              void* d_out, int out_size) {
    const float* x    = (const float*)d_in[0];
    const int*   ei   = (const int*)  d_in[1];
    const float* ew   = (const float*)d_in[2];
    const int*   mask = (const int*)  d_in[3];
    const float* W    = (const float*)d_in[4];
    const float* Wih  = (const float*)d_in[5];
    const float* Whh  = (const float*)d_in[6];
    const float* bih  = (const float*)d_in[7];
    const float* bhh  = (const float*)d_in[8];
    float* out = (float*)d_out;

    float *p_wct, *p_bihp, *p_bhhp;
    __half *p_xh, *p_aggh, *p_whi, *p_wlo, *p_wihphi, *p_wihplo, *p_whhp, *p_wcth;
    cudaGetSymbolAddress((void**)&p_wct,    d_Wct);
    cudaGetSymbolAddress((void**)&p_bihp,   d_bihp);
    cudaGetSymbolAddress((void**)&p_bhhp,   d_bhhp);
    cudaGetSymbolAddress((void**)&p_xh,     d_xh);
    cudaGetSymbolAddress((void**)&p_aggh,   d_aggh);
    cudaGetSymbolAddress((void**)&p_whi,    d_Whi);
    cudaGetSymbolAddress((void**)&p_wlo,    d_Wlo);
    cudaGetSymbolAddress((void**)&p_wihphi, d_Wihphi);
    cudaGetSymbolAddress((void**)&p_wihplo, d_Wihplo);
    cudaGetSymbolAddress((void**)&p_whhp,   d_Whhp);
    cudaGetSymbolAddress((void**)&p_wcth,   d_Wcth);

    cudaFuncSetAttribute(gemm_wct,  cudaFuncAttributeMaxDynamicSharedMemorySize, WCT_SMEM);
    cudaFuncSetAttribute(gemm2_gru, cudaFuncAttributeMaxDynamicSharedMemorySize, FUSE_SMEM);

    // CSR build
    k_zero<<<(NODES + 255) / 256, 256>>>();
    k_count<<<EDGES / 256, 256>>>(ei, mask);
    k_scan<<<1, 1024>>>();
    k_fill<<<EDGES / 256, 256>>>(ei, mask, ew);

    // rounds / splits / permutes
    k_round_x<<<(NODES * Dd / 2 + 255) / 256, 256>>>(x);
    k_split_W<<<(Dd * Dd / 2 + 255) / 256, 256>>>(W);
    k_permsplit<<<(G3D * Dd / 2 + 255) / 256, 256>>>(Wih, Whh, bih, bhh);

    // Wct = Wih(perm) @ W^T : accurate 3-product
    {
        dim3 grid(Dd / 128, G3D / 128);     // (2, 6)
        gemm_wct<<<grid, 256, WCT_SMEM>>>(p_wihphi, p_wihplo, p_whi, p_wlo, p_wct, Dd, Dd);
    }
    k_round_wct<<<(G3D * Dd / 2 + 255) / 256, 256>>>();

    // aggx (fp16 gather, fp32 accumulate, fp16 store)
    k_aggregate<<<NODES, 64>>>();

    // fused: gi = aggx @ Wct^T, gh = x @ Whh^T, register GRU -> out
    {
        dim3 grid(G3D / 96, NODES / 128);   // (8, 256)
        gemm2_gru<<<grid, 256, FUSE_SMEM>>>(p_aggh, p_wcth, p_xh, p_whhp,
                                            p_bihp, p_bhhp, x, mask, out, Dd);
    }
}